// round 1
// baseline (speedup 1.0000x reference)
#include <cuda_runtime.h>
#include <math.h>

#define Bq  8
#define Mq  1024
#define Hq  1024
#define NHq 16
#define HDq 64

// -------- scratch (device globals: no allocations allowed) --------
__device__ float g_Q[Bq*NHq*Mq*HDq];
__device__ float g_K[Bq*NHq*Mq*HDq];
__device__ float g_V[Bq*NHq*Mq*HDq];
__device__ float g_G[Bq*NHq*Mq*HDq];
__device__ float g_ctx[Bq*NHq*Mq*HDq];
__device__ float g_fbar[Bq*Hq];

// =================================================================
// sigma = softplus(relu(x@Wu1+bu1)@Wu2+bu2) + 1e-6   per (b,m) row
// =================================================================
__global__ __launch_bounds__(256) void sigma_kernel(
    const float* __restrict__ x, const float* __restrict__ Wu1,
    const float* __restrict__ bu1, const float* __restrict__ Wu2,
    const float* __restrict__ bu2, float* __restrict__ sigma_out)
{
    __shared__ float xs[1024];
    __shared__ float red[256];
    int row = blockIdx.x;           // 0..8191  (= b*1024+m)
    int t = threadIdx.x;            // 0..255
    ((float4*)xs)[t] = ((const float4*)(x + (size_t)row*1024))[t];
    __syncthreads();

    float acc = bu1[t];
    #pragma unroll 4
    for (int k = 0; k < 1024; k++) acc = fmaf(xs[k], Wu1[k*256 + t], acc);
    acc = fmaxf(acc, 0.f);
    red[t] = acc * Wu2[t];
    __syncthreads();
    for (int s = 128; s > 0; s >>= 1) {
        if (t < s) red[t] += red[t + s];
        __syncthreads();
    }
    if (t == 0) {
        float zv = red[0] + bu2[0];
        float sp = (zv > 20.f) ? zv : log1pf(expf(zv));
        sigma_out[row] = sp + 1e-6f;
    }
}

// =================================================================
// Projections: C = X @ W + b  (optionally sigmoid), permuted store
// to [b,h,m,d].  128x128x8 tile, 256 threads, 8x8 microtile.
// blockIdx.z: 0=Q 1=K 2=V 3=G(sigmoid)
// =================================================================
__global__ __launch_bounds__(256) void proj_kernel(
    const float* __restrict__ X,
    const float* __restrict__ Wq, const float* __restrict__ bq_,
    const float* __restrict__ Wk, const float* __restrict__ bk_,
    const float* __restrict__ Wv, const float* __restrict__ bv_,
    const float* __restrict__ Wg, const float* __restrict__ bg_)
{
    const float* W; const float* bias; float* out; int sig = 0;
    if      (blockIdx.z == 0) { W = Wq; bias = bq_; out = g_Q; }
    else if (blockIdx.z == 1) { W = Wk; bias = bk_; out = g_K; }
    else if (blockIdx.z == 2) { W = Wv; bias = bv_; out = g_V; }
    else                      { W = Wg; bias = bg_; out = g_G; sig = 1; }

    __shared__ float As[8][132];   // [k][m], padded
    __shared__ float Bs[8][128];   // [k][n]
    int t  = threadIdx.x;
    int mb = blockIdx.y * 128;
    int nb = blockIdx.x * 128;
    int lrow = t >> 1;             // 0..127 (X tile row)
    int lk   = (t & 1) * 4;        // 0 or 4
    int wk   = t >> 5;             // 0..7 (W tile k-row)
    int wn   = (t & 31) * 4;       // 0..124
    int ty = t >> 4, tx = t & 15;

    float acc[8][8];
    #pragma unroll
    for (int i = 0; i < 8; i++)
        #pragma unroll
        for (int j = 0; j < 8; j++) acc[i][j] = 0.f;

    const float* xp = X + (size_t)(mb + lrow)*1024 + lk;
    const float* wp = W + (size_t)wk*1024 + nb + wn;

    for (int kb = 0; kb < 1024; kb += 8) {
        float4 xa = *(const float4*)(xp + kb);
        float4 wb = *(const float4*)(wp + (size_t)kb*1024);
        __syncthreads();
        As[lk+0][lrow] = xa.x; As[lk+1][lrow] = xa.y;
        As[lk+2][lrow] = xa.z; As[lk+3][lrow] = xa.w;
        *(float4*)&Bs[wk][wn] = wb;
        __syncthreads();
        #pragma unroll
        for (int kk = 0; kk < 8; kk++) {
            float a[8], bb[8];
            *(float4*)(a)    = *(const float4*)&As[kk][ty*8];
            *(float4*)(a+4)  = *(const float4*)&As[kk][ty*8+4];
            *(float4*)(bb)   = *(const float4*)&Bs[kk][tx*8];
            *(float4*)(bb+4) = *(const float4*)&Bs[kk][tx*8+4];
            #pragma unroll
            for (int i = 0; i < 8; i++)
                #pragma unroll
                for (int j = 0; j < 8; j++)
                    acc[i][j] = fmaf(a[i], bb[j], acc[i][j]);
        }
    }

    // epilogue: bias (+sigmoid), permuted store [b,h,m,d]
    int c0 = nb + tx*8;            // 8 consecutive cols stay within one head
    int hh = c0 >> 6;
    int dd = c0 & 63;
    float bias8[8];
    #pragma unroll
    for (int j = 0; j < 8; j++) bias8[j] = bias[c0 + j];
    #pragma unroll
    for (int i = 0; i < 8; i++) {
        int gr = mb + ty*8 + i;
        int bb_ = gr >> 10;
        int mm  = gr & 1023;
        float v[8];
        #pragma unroll
        for (int j = 0; j < 8; j++) {
            float vv = acc[i][j] + bias8[j];
            if (sig) vv = 1.f / (1.f + expf(-vv));
            v[j] = vv;
        }
        float* op = out + ((size_t)(bb_*NHq + hh)*Mq + mm)*HDq + dd;
        *(float4*)(op)     = *(float4*)(v);
        *(float4*)(op + 4) = *(float4*)(v + 4);
    }
}

// =================================================================
// Fused attention per (b, h, 32-row m-tile):
//  S = (Q Kt) * (0.125/sig_m) * (1/sig_n)  -> smem (32x1024)
//  softmax rows, write attn, ctx = P @ V, gate, store ctx
// =================================================================
#define SSTR 1032
#define ATTN_SMEM_FLOATS (32*SSTR + 64*33 + 64*68 + 1024 + 32)
#define ATTN_SMEM_BYTES  (ATTN_SMEM_FLOATS * 4)

__global__ __launch_bounds__(256) void attn_kernel(
    const float* __restrict__ sigma, float* __restrict__ attn_out)
{
    extern __shared__ float sm[];
    float* Ss     = sm;                    // 32 x 1032
    float* Qs     = Ss + 32*SSTR;          // [d][r] 64 x 33
    float* KVs    = Qs + 64*33;            // 64 x 68 (K transposed / V natural)
    float* invn   = KVs + 64*68;           // 1024
    float* rowfac = invn + 1024;           // 32
    __shared__ float red[256];
    __shared__ float rowmax[32];
    __shared__ float rinv_s[32];

    int t  = threadIdx.x;
    int m0 = blockIdx.x * 32;
    int h  = blockIdx.y;
    int b  = blockIdx.z;
    int bh = b*NHq + h;
    const float* Qg = g_Q + (size_t)bh*Mq*HDq;
    const float* Kg = g_K + (size_t)bh*Mq*HDq;
    const float* Vg = g_V + (size_t)bh*Mq*HDq;
    const float* Gg = g_G + (size_t)bh*Mq*HDq;
    float*       Cg = g_ctx + (size_t)bh*Mq*HDq;
    const float* sigb = sigma + b*Mq;

    for (int i = t; i < 1024; i += 256) invn[i] = 1.0f / sigb[i];
    if (t < 32) rowfac[t] = 0.125f / sigb[m0 + t];

    {   // Q tile transposed: Qs[d][r]
        int r  = t >> 3;
        int d0 = (t & 7) * 8;
        const float* qrow = Qg + (size_t)(m0 + r)*HDq + d0;
        float4 v0 = *(const float4*)(qrow);
        float4 v1 = *(const float4*)(qrow + 4);
        Qs[(d0+0)*33 + r] = v0.x; Qs[(d0+1)*33 + r] = v0.y;
        Qs[(d0+2)*33 + r] = v0.z; Qs[(d0+3)*33 + r] = v0.w;
        Qs[(d0+4)*33 + r] = v1.x; Qs[(d0+5)*33 + r] = v1.y;
        Qs[(d0+6)*33 + r] = v1.z; Qs[(d0+7)*33 + r] = v1.w;
    }

    int ty = t >> 4, tx = t & 15;
    int r0 = ty*2, r1 = ty*2 + 1;

    // ---- S = scaled Q Kt ----
    for (int nc = 0; nc < 16; nc++) {
        int nbase = nc * 64;
        __syncthreads();               // KVs free (1st iter also covers Qs/invn)
        {   // K chunk transposed: KVs[d][n]
            int n  = t >> 2;
            int d0 = (t & 3) * 16;
            const float* krow = Kg + (size_t)(nbase + n)*HDq + d0;
            #pragma unroll
            for (int j = 0; j < 16; j += 4) {
                float4 v = *(const float4*)(krow + j);
                KVs[(d0+j+0)*68 + n] = v.x;
                KVs[(d0+j+1)*68 + n] = v.y;
                KVs[(d0+j+2)*68 + n] = v.z;
                KVs[(d0+j+3)*68 + n] = v.w;
            }
        }
        __syncthreads();
        float s0[4] = {0,0,0,0}, s1[4] = {0,0,0,0};
        #pragma unroll 8
        for (int d = 0; d < 64; d++) {
            float a0 = Qs[d*33 + r0];
            float a1 = Qs[d*33 + r1];
            float4 bb = *(const float4*)&KVs[d*68 + tx*4];
            s0[0] = fmaf(a0, bb.x, s0[0]); s0[1] = fmaf(a0, bb.y, s0[1]);
            s0[2] = fmaf(a0, bb.z, s0[2]); s0[3] = fmaf(a0, bb.w, s0[3]);
            s1[0] = fmaf(a1, bb.x, s1[0]); s1[1] = fmaf(a1, bb.y, s1[1]);
            s1[2] = fmaf(a1, bb.z, s1[2]); s1[3] = fmaf(a1, bb.w, s1[3]);
        }
        float f0 = rowfac[r0], f1 = rowfac[r1];
        float4 iv = *(const float4*)&invn[nbase + tx*4];
        float4 o0, o1;
        o0.x = s0[0]*f0*iv.x; o0.y = s0[1]*f0*iv.y;
        o0.z = s0[2]*f0*iv.z; o0.w = s0[3]*f0*iv.w;
        o1.x = s1[0]*f1*iv.x; o1.y = s1[1]*f1*iv.y;
        o1.z = s1[2]*f1*iv.z; o1.w = s1[3]*f1*iv.w;
        *(float4*)&Ss[r0*SSTR + nbase + tx*4] = o0;
        *(float4*)&Ss[r1*SSTR + nbase + tx*4] = o1;
    }
    __syncthreads();

    // ---- softmax (exact, 8 threads per row, stride-8 conflict-free) ----
    {
        int r = t >> 3;
        int q = t & 7;
        float* srow = Ss + r*SSTR;
        float mx = -1e30f;
        for (int c = q; c < 1024; c += 8) mx = fmaxf(mx, srow[c]);
        red[t] = mx;
        __syncthreads();
        if (q == 0) {
            float m = red[t];
            #pragma unroll
            for (int j = 1; j < 8; j++) m = fmaxf(m, red[t + j]);
            rowmax[r] = m;
        }
        __syncthreads();
        float rm = rowmax[r];
        float sum = 0.f;
        for (int c = q; c < 1024; c += 8) {
            float e = __expf(srow[c] - rm);
            srow[c] = e;
            sum += e;
        }
        red[t] = sum;
        __syncthreads();
        if (q == 0) {
            float s = red[t];
            #pragma unroll
            for (int j = 1; j < 8; j++) s += red[t + j];
            rinv_s[r] = 1.0f / s;
        }
        __syncthreads();
    }

    // ---- normalize + write attn (coalesced float4) ----
    {
        float* aout = attn_out + ((size_t)bh*Mq + m0) * 1024;
        #pragma unroll 1
        for (int r = 0; r < 32; r++) {
            float ri = rinv_s[r];
            float4 p = *(float4*)&Ss[r*SSTR + t*4];
            p.x *= ri; p.y *= ri; p.z *= ri; p.w *= ri;
            *(float4*)&Ss[r*SSTR + t*4] = p;
            *(float4*)&aout[(size_t)r*1024 + t*4] = p;
        }
    }

    // ---- ctx = P @ V ----
    float c0a[4] = {0,0,0,0}, c1a[4] = {0,0,0,0};
    for (int nc = 0; nc < 16; nc++) {
        __syncthreads();
        {   // V chunk natural: KVs[n][d]
            int n  = t >> 2;
            int d0 = (t & 3) * 16;
            const float* vrow = Vg + (size_t)(nc*64 + n)*HDq + d0;
            #pragma unroll
            for (int j = 0; j < 16; j += 4)
                *(float4*)&KVs[n*68 + d0 + j] = *(const float4*)(vrow + j);
        }
        __syncthreads();
        const float* p0 = Ss + r0*SSTR + nc*64;
        const float* p1 = Ss + r1*SSTR + nc*64;
        #pragma unroll 8
        for (int n = 0; n < 64; n++) {
            float a0 = p0[n], a1 = p1[n];
            float4 v = *(const float4*)&KVs[n*68 + tx*4];
            c0a[0] = fmaf(a0, v.x, c0a[0]); c0a[1] = fmaf(a0, v.y, c0a[1]);
            c0a[2] = fmaf(a0, v.z, c0a[2]); c0a[3] = fmaf(a0, v.w, c0a[3]);
            c1a[0] = fmaf(a1, v.x, c1a[0]); c1a[1] = fmaf(a1, v.y, c1a[1]);
            c1a[2] = fmaf(a1, v.z, c1a[2]); c1a[3] = fmaf(a1, v.w, c1a[3]);
        }
    }

    // ---- gate + store ctx [b,h,m,d] ----
    {
        size_t i0 = (size_t)(m0 + r0)*HDq + tx*4;
        size_t i1 = (size_t)(m0 + r1)*HDq + tx*4;
        float4 g0 = *(const float4*)(Gg + i0);
        float4 g1 = *(const float4*)(Gg + i1);
        float4 o0, o1;
        o0.x = c0a[0]*g0.x; o0.y = c0a[1]*g0.y; o0.z = c0a[2]*g0.z; o0.w = c0a[3]*g0.w;
        o1.x = c1a[0]*g1.x; o1.y = c1a[1]*g1.y; o1.z = c1a[2]*g1.z; o1.w = c1a[3]*g1.w;
        *(float4*)(Cg + i0) = o0;
        *(float4*)(Cg + i1) = o1;
    }
}

// =================================================================
// fbar[b, h*64+d] = mean_m ctx[b,h,m,d]
// =================================================================
__global__ __launch_bounds__(256) void mean_kernel()
{
    int idx = blockIdx.x * 256 + threadIdx.x;  // 0..8191
    int b = idx >> 10;
    int c = idx & 1023;
    int h = c >> 6;
    int d = c & 63;
    const float* p = g_ctx + (size_t)(b*NHq + h)*Mq*HDq + d;
    float s = 0.f;
    #pragma unroll 4
    for (int m = 0; m < 1024; m++) s += p[(size_t)m*64];
    g_fbar[idx] = s * (1.0f/1024.0f);
}

// =================================================================
// z[b] = fbar[b] @ Wo + bo
// =================================================================
__global__ __launch_bounds__(256) void z_kernel(
    const float* __restrict__ Wo, const float* __restrict__ bo_,
    float* __restrict__ z)
{
    int n = blockIdx.x * 256 + threadIdx.x;  // 0..1023
    int b = blockIdx.y;
    const float* f = g_fbar + b*1024;
    float acc = bo_[n];
    #pragma unroll 4
    for (int k = 0; k < 1024; k++) acc = fmaf(f[k], Wo[(size_t)k*1024 + n], acc);
    z[(size_t)b*1024 + n] = acc;
}

// =================================================================
extern "C" void kernel_launch(void* const* d_in, const int* in_sizes, int n_in,
                              void* d_out, int out_size)
{
    const float* x   = (const float*)d_in[0];
    const float* Wq  = (const float*)d_in[1];
    const float* bq  = (const float*)d_in[2];
    const float* Wk  = (const float*)d_in[3];
    const float* bk  = (const float*)d_in[4];
    const float* Wv  = (const float*)d_in[5];
    const float* bv  = (const float*)d_in[6];
    const float* Wg  = (const float*)d_in[7];
    const float* bg  = (const float*)d_in[8];
    const float* Wo  = (const float*)d_in[9];
    const float* bo  = (const float*)d_in[10];
    const float* Wu1 = (const float*)d_in[11];
    const float* bu1 = (const float*)d_in[12];
    const float* Wu2 = (const float*)d_in[13];
    const float* bu2 = (const float*)d_in[14];

    float* out       = (float*)d_out;
    float* z_out     = out;                                    // 8*1024
    float* attn_out  = out + 8192;                             // 8*16*1024*1024
    float* sigma_out = out + 8192 + (size_t)Bq*NHq*Mq*Mq;      // 8*1024

    cudaFuncSetAttribute(attn_kernel,
        cudaFuncAttributeMaxDynamicSharedMemorySize, ATTN_SMEM_BYTES);

    sigma_kernel<<<8192, 256>>>(x, Wu1, bu1, Wu2, bu2, sigma_out);
    proj_kernel<<<dim3(8, 64, 4), 256>>>(x, Wq, bq, Wk, bk, Wv, bv, Wg, bg);
    attn_kernel<<<dim3(32, 16, 8), 256, ATTN_SMEM_BYTES>>>(sigma_out, attn_out);
    mean_kernel<<<32, 256>>>();
    z_kernel<<<dim3(4, 8), 256>>>(Wo, bo, z_out);
}

// round 3
// speedup vs baseline: 1.4045x; 1.4045x over previous
#include <cuda_runtime.h>
#include <cuda_bf16.h>
#include <math.h>
#include <stdint.h>

#define Bq  8
#define Mq  1024
#define Hq  1024
#define NHq 16
#define HDq 64

// -------- scratch (device globals: no allocations allowed) --------
__device__ float g_Q[Bq*NHq*Mq*HDq];
__device__ float g_K[Bq*NHq*Mq*HDq];
__device__ float g_V[Bq*NHq*Mq*HDq];
__device__ float g_G[Bq*NHq*Mq*HDq];
__device__ float g_ctx[Bq*NHq*Mq*HDq];
__device__ float g_fbar[Bq*Hq];

// bf16 hi/lo split operands
__device__ __nv_bfloat16 g_Xhi[Bq*Mq*Hq];
__device__ __nv_bfloat16 g_Xlo[Bq*Mq*Hq];
__device__ __nv_bfloat16 g_Whi[4*Hq*Hq];      // transposed [n][k]
__device__ __nv_bfloat16 g_Wlo[4*Hq*Hq];
__device__ __nv_bfloat16 g_U1hi[256*Hq];      // transposed [n][k]
__device__ __nv_bfloat16 g_U1lo[256*Hq];

extern __shared__ char s_dyn[];

// ================= helpers =================
__device__ __forceinline__ uint32_t smem_u32(const void* p) {
    uint32_t a;
    asm("{ .reg .u64 t; cvta.to.shared.u64 t, %1; cvt.u32.u64 %0, t; }"
        : "=r"(a) : "l"(p));
    return a;
}
__device__ __forceinline__ void ldsm4(uint32_t* r, uint32_t addr) {
    asm volatile("ldmatrix.sync.aligned.m8n8.x4.shared.b16 {%0,%1,%2,%3}, [%4];"
        : "=r"(r[0]), "=r"(r[1]), "=r"(r[2]), "=r"(r[3]) : "r"(addr));
}
__device__ __forceinline__ void mma16816(float* d, const uint32_t* a, const uint32_t* b) {
    asm volatile("mma.sync.aligned.m16n8k16.row.col.f32.bf16.bf16.f32 "
        "{%0,%1,%2,%3}, {%4,%5,%6,%7}, {%8,%9}, {%0,%1,%2,%3};"
        : "+f"(d[0]), "+f"(d[1]), "+f"(d[2]), "+f"(d[3])
        : "r"(a[0]), "r"(a[1]), "r"(a[2]), "r"(a[3]), "r"(b[0]), "r"(b[1]));
}

// ================= prep: split X into bf16 hi/lo =================
__global__ __launch_bounds__(256) void splitx_kernel(const float* __restrict__ x)
{
    size_t i = ((size_t)blockIdx.x * 256 + threadIdx.x) * 4;
    float4 v = *(const float4*)(x + i);
    __nv_bfloat16 h0 = __float2bfloat16(v.x);
    __nv_bfloat16 h1 = __float2bfloat16(v.y);
    __nv_bfloat16 h2 = __float2bfloat16(v.z);
    __nv_bfloat16 h3 = __float2bfloat16(v.w);
    __nv_bfloat16 l0 = __float2bfloat16(v.x - __bfloat162float(h0));
    __nv_bfloat16 l1 = __float2bfloat16(v.y - __bfloat162float(h1));
    __nv_bfloat16 l2 = __float2bfloat16(v.z - __bfloat162float(h2));
    __nv_bfloat16 l3 = __float2bfloat16(v.w - __bfloat162float(h3));
    *(__nv_bfloat162*)(g_Xhi + i)     = __nv_bfloat162(h0, h1);
    *(__nv_bfloat162*)(g_Xhi + i + 2) = __nv_bfloat162(h2, h3);
    *(__nv_bfloat162*)(g_Xlo + i)     = __nv_bfloat162(l0, l1);
    *(__nv_bfloat162*)(g_Xlo + i + 2) = __nv_bfloat162(l2, l3);
}

// ============ prep: transpose + split W's ([K,N] -> [N,K] bf16 hi/lo) ============
__global__ __launch_bounds__(256) void tsplitw_kernel(
    const float* __restrict__ Wq, const float* __restrict__ Wk,
    const float* __restrict__ Wv, const float* __restrict__ Wg,
    const float* __restrict__ Wu1)
{
    __shared__ float tile[32][33];
    int z = blockIdx.z;
    const float* W; __nv_bfloat16 *oh, *ol; int N;
    if (z < 4) {
        W = (z == 0 ? Wq : z == 1 ? Wk : z == 2 ? Wv : Wg); N = 1024;
        oh = g_Whi + (size_t)z * 1024 * 1024; ol = g_Wlo + (size_t)z * 1024 * 1024;
    } else {
        W = Wu1; N = 256; oh = g_U1hi; ol = g_U1lo;
    }
    int kb = blockIdx.x * 32, nb = blockIdx.y * 32;
    if (nb >= N) return;
    int t = threadIdx.x, tx = t & 31, ty = t >> 5;
    #pragma unroll
    for (int i = 0; i < 4; i++)
        tile[ty + 8*i][tx] = W[(size_t)(kb + ty + 8*i) * N + nb + tx];
    __syncthreads();
    #pragma unroll
    for (int i = 0; i < 4; i++) {
        float v = tile[tx][ty + 8*i];
        __nv_bfloat16 h = __float2bfloat16(v);
        __nv_bfloat16 l = __float2bfloat16(v - __bfloat162float(h));
        size_t oidx = (size_t)(nb + ty + 8*i) * 1024 + kb + tx;
        oh[oidx] = h; ol[oidx] = l;
    }
}

// ================= mma.sync GEMM core =================
// CTA computes 128(m) x 256(n) of A[.,1024] @ W_t[n][k], hi/lo 3-pass.
// 512 threads = 16 warps (wm 0..3 x wn 0..3); warp = 32m x 64n.
#define ASTR 40
#define BSTR 40
#define A_ELE (128*ASTR)                 // 5120 bf16
#define B_ELE (256*BSTR)                 // 10240 bf16
#define BUF_ELE (2*A_ELE + 2*B_ELE)      // 30720 bf16
#define GEMM_SMEM (2*BUF_ELE*2)          // 122880 B

__device__ __forceinline__ void mma_gemm_main(
    const __nv_bfloat16* __restrict__ Ah, const __nv_bfloat16* __restrict__ Al,
    const __nv_bfloat16* __restrict__ Bh, const __nv_bfloat16* __restrict__ Bl,
    int mb, int nb, float acc[2][8][4])
{
    __nv_bfloat16* sm = (__nv_bfloat16*)s_dyn;
    const uint32_t smb = smem_u32(sm);
    const int t = threadIdx.x, lane = t & 31, wid = t >> 5;
    const int wm = wid & 3, wn = wid >> 2;

    // ldmatrix per-thread offsets (in bf16 elements)
    const int aoff = (wm*32 + (lane & 15))*ASTR + ((lane >> 4) << 3);
    const int boff = (wn*64 + (lane & 7) + ((lane >> 4) << 3))*BSTR
                   + (((lane >> 3) & 1) << 3);

    // LDG/STS coords
    const int arow = t >> 2;           // 0..127
    const int aseg = (t & 3) * 8;      // 0,8,16,24 (bf16 elems)

    const __nv_bfloat16* pAh = Ah + (size_t)(mb + arow)*1024 + aseg;
    const __nv_bfloat16* pAl = Al + (size_t)(mb + arow)*1024 + aseg;
    const __nv_bfloat16* pB0h = Bh + (size_t)(nb + arow)*1024 + aseg;
    const __nv_bfloat16* pB1h = Bh + (size_t)(nb + arow + 128)*1024 + aseg;
    const __nv_bfloat16* pB0l = Bl + (size_t)(nb + arow)*1024 + aseg;
    const __nv_bfloat16* pB1l = Bl + (size_t)(nb + arow + 128)*1024 + aseg;

    const int stA = arow*ASTR + aseg;
    const int stB0 = arow*BSTR + aseg;
    const int stB1 = (arow + 128)*BSTR + aseg;

    uint4 ra_h, ra_l, rb0h, rb1h, rb0l, rb1l;
    ra_h = *(const uint4*)(pAh);  ra_l = *(const uint4*)(pAl);
    rb0h = *(const uint4*)(pB0h); rb1h = *(const uint4*)(pB1h);
    rb0l = *(const uint4*)(pB0l); rb1l = *(const uint4*)(pB1l);

    for (int c = 0; c < 32; c++) {
        const int bo = (c & 1) * BUF_ELE;
        *(uint4*)(sm + bo + stA)                    = ra_h;
        *(uint4*)(sm + bo + A_ELE + stA)            = ra_l;
        *(uint4*)(sm + bo + 2*A_ELE + stB0)         = rb0h;
        *(uint4*)(sm + bo + 2*A_ELE + stB1)         = rb1h;
        *(uint4*)(sm + bo + 2*A_ELE + B_ELE + stB0) = rb0l;
        *(uint4*)(sm + bo + 2*A_ELE + B_ELE + stB1) = rb1l;
        __syncthreads();
        if (c < 31) {
            int kb = (c + 1) * 32;
            ra_h = *(const uint4*)(pAh + kb);  ra_l = *(const uint4*)(pAl + kb);
            rb0h = *(const uint4*)(pB0h + kb); rb1h = *(const uint4*)(pB1h + kb);
            rb0l = *(const uint4*)(pB0l + kb); rb1l = *(const uint4*)(pB1l + kb);
        }
        #pragma unroll
        for (int ks = 0; ks < 2; ks++) {
            const int koff = ks * 16;
            uint32_t ah[2][4], al2[2][4], bhf[4][4], blf[4][4];
            #pragma unroll
            for (int mi = 0; mi < 2; mi++) {
                uint32_t ad = smb + (uint32_t)(bo + aoff + mi*16*ASTR + koff) * 2;
                ldsm4(ah[mi], ad);
                ldsm4(al2[mi], ad + A_ELE*2);
            }
            #pragma unroll
            for (int n2 = 0; n2 < 4; n2++) {
                uint32_t bd = smb + (uint32_t)(bo + 2*A_ELE + boff + n2*16*BSTR + koff) * 2;
                ldsm4(bhf[n2], bd);
                ldsm4(blf[n2], bd + B_ELE*2);
            }
            #pragma unroll
            for (int mi = 0; mi < 2; mi++)
                #pragma unroll
                for (int ni = 0; ni < 8; ni++)
                    mma16816(acc[mi][ni], ah[mi], &bhf[ni >> 1][(ni & 1) * 2]);
            #pragma unroll
            for (int mi = 0; mi < 2; mi++)
                #pragma unroll
                for (int ni = 0; ni < 8; ni++)
                    mma16816(acc[mi][ni], ah[mi], &blf[ni >> 1][(ni & 1) * 2]);
            #pragma unroll
            for (int mi = 0; mi < 2; mi++)
                #pragma unroll
                for (int ni = 0; ni < 8; ni++)
                    mma16816(acc[mi][ni], al2[mi], &bhf[ni >> 1][(ni & 1) * 2]);
        }
    }
}

// ================= projections via mma =================
__global__ __launch_bounds__(512) void proj_mma_kernel(
    const float* __restrict__ bq_, const float* __restrict__ bk_,
    const float* __restrict__ bv_, const float* __restrict__ bg_)
{
    __shared__ float bias_s[256];
    int t = threadIdx.x, lane = t & 31, wid = t >> 5;
    int wm = wid & 3, wn = wid >> 2;
    int mb = blockIdx.y * 128;
    int nb = blockIdx.x * 256;
    int wsel = blockIdx.z;
    const __nv_bfloat16* Bh = g_Whi + (size_t)wsel * 1024 * 1024;
    const __nv_bfloat16* Bl = g_Wlo + (size_t)wsel * 1024 * 1024;
    const float* bias = wsel == 0 ? bq_ : wsel == 1 ? bk_ : wsel == 2 ? bv_ : bg_;
    float* out = wsel == 0 ? g_Q : wsel == 1 ? g_K : wsel == 2 ? g_V : g_G;
    int sig = (wsel == 3);

    if (t < 256) bias_s[t] = bias[nb + t];
    __syncthreads();

    float acc[2][8][4];
    #pragma unroll
    for (int mi = 0; mi < 2; mi++)
        #pragma unroll
        for (int ni = 0; ni < 8; ni++)
            #pragma unroll
            for (int j = 0; j < 4; j++) acc[mi][ni][j] = 0.f;

    mma_gemm_main(g_Xhi, g_Xlo, Bh, Bl, mb, nb, acc);

    int b = mb >> 10, mloc = mb & 1023;
    int hh = (nb >> 6) + wn;
    float* op = out + ((size_t)(b*NHq + hh)*Mq + mloc)*HDq;
    int r0 = wm*32 + (lane >> 2);
    int c0 = (lane & 3) * 2;
    #pragma unroll
    for (int mi = 0; mi < 2; mi++) {
        #pragma unroll
        for (int ni = 0; ni < 8; ni++) {
            int col = ni*8 + c0;
            float b0 = bias_s[wn*64 + col], b1 = bias_s[wn*64 + col + 1];
            float v0 = acc[mi][ni][0] + b0, v1 = acc[mi][ni][1] + b1;
            float v2 = acc[mi][ni][2] + b0, v3 = acc[mi][ni][3] + b1;
            if (sig) {
                v0 = 1.f/(1.f + __expf(-v0)); v1 = 1.f/(1.f + __expf(-v1));
                v2 = 1.f/(1.f + __expf(-v2)); v3 = 1.f/(1.f + __expf(-v3));
            }
            int row = r0 + mi*16;
            *(float2*)(op + (size_t)row*64 + col)     = make_float2(v0, v1);
            *(float2*)(op + (size_t)(row+8)*64 + col) = make_float2(v2, v3);
        }
    }
}

// ================= sigma via mma (N=256, fused epilogue) =================
__global__ __launch_bounds__(512) void sigma_mma_kernel(
    const float* __restrict__ bu1, const float* __restrict__ Wu2,
    const float* __restrict__ bu2, float* __restrict__ sigma_out)
{
    __shared__ float bu1_s[256], wu2_s[256];
    __shared__ float red[128][4];
    int t = threadIdx.x, lane = t & 31, wid = t >> 5;
    int wm = wid & 3, wn = wid >> 2;
    int mb = blockIdx.x * 128;

    if (t < 256) { bu1_s[t] = bu1[t]; wu2_s[t] = Wu2[t]; }
    __syncthreads();

    float acc[2][8][4];
    #pragma unroll
    for (int mi = 0; mi < 2; mi++)
        #pragma unroll
        for (int ni = 0; ni < 8; ni++)
            #pragma unroll
            for (int j = 0; j < 4; j++) acc[mi][ni][j] = 0.f;

    mma_gemm_main(g_Xhi, g_Xlo, g_U1hi, g_U1lo, mb, 0, acc);

    int c0 = (lane & 3) * 2;
    float p[2][2] = {{0.f,0.f},{0.f,0.f}};
    #pragma unroll
    for (int mi = 0; mi < 2; mi++) {
        #pragma unroll
        for (int ni = 0; ni < 8; ni++) {
            int col = wn*64 + ni*8 + c0;
            float w0 = wu2_s[col], w1 = wu2_s[col+1];
            float a0 = fmaxf(acc[mi][ni][0] + bu1_s[col],   0.f);
            float a1 = fmaxf(acc[mi][ni][1] + bu1_s[col+1], 0.f);
            float a2 = fmaxf(acc[mi][ni][2] + bu1_s[col],   0.f);
            float a3 = fmaxf(acc[mi][ni][3] + bu1_s[col+1], 0.f);
            p[mi][0] += a0*w0 + a1*w1;
            p[mi][1] += a2*w0 + a3*w1;
        }
    }
    #pragma unroll
    for (int mi = 0; mi < 2; mi++)
        #pragma unroll
        for (int j = 0; j < 2; j++) {
            p[mi][j] += __shfl_xor_sync(0xFFFFFFFF, p[mi][j], 1);
            p[mi][j] += __shfl_xor_sync(0xFFFFFFFF, p[mi][j], 2);
        }
    if ((lane & 3) == 0) {
        #pragma unroll
        for (int mi = 0; mi < 2; mi++)
            #pragma unroll
            for (int j = 0; j < 2; j++)
                red[wm*32 + mi*16 + j*8 + (lane >> 2)][wn] = p[mi][j];
    }
    __syncthreads();
    if (t < 128) {
        float zv = red[t][0] + red[t][1] + red[t][2] + red[t][3] + bu2[0];
        float sp = (zv > 20.f) ? zv : log1pf(expf(zv));
        sigma_out[mb + t] = sp + 1e-6f;
    }
}

// =================================================================
// Fused attention per (b, h, 32-row m-tile)  [unchanged]
// =================================================================
#define SSTR 1032
#define ATTN_SMEM_FLOATS (32*SSTR + 64*33 + 64*68 + 1024 + 32)
#define ATTN_SMEM_BYTES  (ATTN_SMEM_FLOATS * 4)

__global__ __launch_bounds__(256) void attn_kernel(
    const float* __restrict__ sigma, float* __restrict__ attn_out)
{
    float* sm = (float*)s_dyn;
    float* Ss     = sm;
    float* Qs     = Ss + 32*SSTR;
    float* KVs    = Qs + 64*33;
    float* invn   = KVs + 64*68;
    float* rowfac = invn + 1024;
    __shared__ float red[256];
    __shared__ float rowmax[32];
    __shared__ float rinv_s[32];

    int t  = threadIdx.x;
    int m0 = blockIdx.x * 32;
    int h  = blockIdx.y;
    int b  = blockIdx.z;
    int bh = b*NHq + h;
    const float* Qg = g_Q + (size_t)bh*Mq*HDq;
    const float* Kg = g_K + (size_t)bh*Mq*HDq;
    const float* Vg = g_V + (size_t)bh*Mq*HDq;
    const float* Gg = g_G + (size_t)bh*Mq*HDq;
    float*       Cg = g_ctx + (size_t)bh*Mq*HDq;
    const float* sigb = sigma + b*Mq;

    for (int i = t; i < 1024; i += 256) invn[i] = 1.0f / sigb[i];
    if (t < 32) rowfac[t] = 0.125f / sigb[m0 + t];

    {
        int r  = t >> 3;
        int d0 = (t & 7) * 8;
        const float* qrow = Qg + (size_t)(m0 + r)*HDq + d0;
        float4 v0 = *(const float4*)(qrow);
        float4 v1 = *(const float4*)(qrow + 4);
        Qs[(d0+0)*33 + r] = v0.x; Qs[(d0+1)*33 + r] = v0.y;
        Qs[(d0+2)*33 + r] = v0.z; Qs[(d0+3)*33 + r] = v0.w;
        Qs[(d0+4)*33 + r] = v1.x; Qs[(d0+5)*33 + r] = v1.y;
        Qs[(d0+6)*33 + r] = v1.z; Qs[(d0+7)*33 + r] = v1.w;
    }

    int ty = t >> 4, tx = t & 15;
    int r0 = ty*2, r1 = ty*2 + 1;

    for (int nc = 0; nc < 16; nc++) {
        int nbase = nc * 64;
        __syncthreads();
        {
            int n  = t >> 2;
            int d0 = (t & 3) * 16;
            const float* krow = Kg + (size_t)(nbase + n)*HDq + d0;
            #pragma unroll
            for (int j = 0; j < 16; j += 4) {
                float4 v = *(const float4*)(krow + j);
                KVs[(d0+j+0)*68 + n] = v.x;
                KVs[(d0+j+1)*68 + n] = v.y;
                KVs[(d0+j+2)*68 + n] = v.z;
                KVs[(d0+j+3)*68 + n] = v.w;
            }
        }
        __syncthreads();
        float s0[4] = {0,0,0,0}, s1[4] = {0,0,0,0};
        #pragma unroll 8
        for (int d = 0; d < 64; d++) {
            float a0 = Qs[d*33 + r0];
            float a1 = Qs[d*33 + r1];
            float4 bb = *(const float4*)&KVs[d*68 + tx*4];
            s0[0] = fmaf(a0, bb.x, s0[0]); s0[1] = fmaf(a0, bb.y, s0[1]);
            s0[2] = fmaf(a0, bb.z, s0[2]); s0[3] = fmaf(a0, bb.w, s0[3]);
            s1[0] = fmaf(a1, bb.x, s1[0]); s1[1] = fmaf(a1, bb.y, s1[1]);
            s1[2] = fmaf(a1, bb.z, s1[2]); s1[3] = fmaf(a1, bb.w, s1[3]);
        }
        float f0 = rowfac[r0], f1 = rowfac[r1];
        float4 iv = *(const float4*)&invn[nbase + tx*4];
        float4 o0, o1;
        o0.x = s0[0]*f0*iv.x; o0.y = s0[1]*f0*iv.y;
        o0.z = s0[2]*f0*iv.z; o0.w = s0[3]*f0*iv.w;
        o1.x = s1[0]*f1*iv.x; o1.y = s1[1]*f1*iv.y;
        o1.z = s1[2]*f1*iv.z; o1.w = s1[3]*f1*iv.w;
        *(float4*)&Ss[r0*SSTR + nbase + tx*4] = o0;
        *(float4*)&Ss[r1*SSTR + nbase + tx*4] = o1;
    }
    __syncthreads();

    {
        int r = t >> 3;
        int q = t & 7;
        float* srow = Ss + r*SSTR;
        float mx = -1e30f;
        for (int c = q; c < 1024; c += 8) mx = fmaxf(mx, srow[c]);
        red[t] = mx;
        __syncthreads();
        if (q == 0) {
            float m = red[t];
            #pragma unroll
            for (int j = 1; j < 8; j++) m = fmaxf(m, red[t + j]);
            rowmax[r] = m;
        }
        __syncthreads();
        float rm = rowmax[r];
        float sum = 0.f;
        for (int c = q; c < 1024; c += 8) {
            float e = __expf(srow[c] - rm);
            srow[c] = e;
            sum += e;
        }
        red[t] = sum;
        __syncthreads();
        if (q == 0) {
            float s = red[t];
            #pragma unroll
            for (int j = 1; j < 8; j++) s += red[t + j];
            rinv_s[r] = 1.0f / s;
        }
        __syncthreads();
    }

    {
        float* aout = attn_out + ((size_t)bh*Mq + m0) * 1024;
        #pragma unroll 1
        for (int r = 0; r < 32; r++) {
            float ri = rinv_s[r];
            float4 p = *(float4*)&Ss[r*SSTR + t*4];
            p.x *= ri; p.y *= ri; p.z *= ri; p.w *= ri;
            *(float4*)&Ss[r*SSTR + t*4] = p;
            *(float4*)&aout[(size_t)r*1024 + t*4] = p;
        }
    }

    float c0a[4] = {0,0,0,0}, c1a[4] = {0,0,0,0};
    for (int nc = 0; nc < 16; nc++) {
        __syncthreads();
        {
            int n  = t >> 2;
            int d0 = (t & 3) * 16;
            const float* vrow = Vg + (size_t)(nc*64 + n)*HDq + d0;
            #pragma unroll
            for (int j = 0; j < 16; j += 4)
                *(float4*)&KVs[n*68 + d0 + j] = *(const float4*)(vrow + j);
        }
        __syncthreads();
        const float* p0 = Ss + r0*SSTR + nc*64;
        const float* p1 = Ss + r1*SSTR + nc*64;
        #pragma unroll 8
        for (int n = 0; n < 64; n++) {
            float a0 = p0[n], a1 = p1[n];
            float4 v = *(const float4*)&KVs[n*68 + tx*4];
            c0a[0] = fmaf(a0, v.x, c0a[0]); c0a[1] = fmaf(a0, v.y, c0a[1]);
            c0a[2] = fmaf(a0, v.z, c0a[2]); c0a[3] = fmaf(a0, v.w, c0a[3]);
            c1a[0] = fmaf(a1, v.x, c1a[0]); c1a[1] = fmaf(a1, v.y, c1a[1]);
            c1a[2] = fmaf(a1, v.z, c1a[2]); c1a[3] = fmaf(a1, v.w, c1a[3]);
        }
    }

    {
        size_t i0 = (size_t)(m0 + r0)*HDq + tx*4;
        size_t i1 = (size_t)(m0 + r1)*HDq + tx*4;
        float4 g0 = *(const float4*)(Gg + i0);
        float4 g1 = *(const float4*)(Gg + i1);
        float4 o0, o1;
        o0.x = c0a[0]*g0.x; o0.y = c0a[1]*g0.y; o0.z = c0a[2]*g0.z; o0.w = c0a[3]*g0.w;
        o1.x = c1a[0]*g1.x; o1.y = c1a[1]*g1.y; o1.z = c1a[2]*g1.z; o1.w = c1a[3]*g1.w;
        *(float4*)(Cg + i0) = o0;
        *(float4*)(Cg + i1) = o1;
    }
}

// ============ mean over m: 1 block per (b,h) ============
__global__ __launch_bounds__(256) void mean_kernel()
{
    __shared__ float red[256];
    int bh = blockIdx.x;
    int t = threadIdx.x;
    int d = t & 63, grp = t >> 6;
    const float* p = g_ctx + (size_t)bh*Mq*HDq + grp*64 + d;
    float s = 0.f;
    #pragma unroll 8
    for (int m = 0; m < 256; m++) s += p[(size_t)m*256];
    red[t] = s;
    __syncthreads();
    if (t < 64)
        g_fbar[(size_t)bh*64 + d] =
            (red[t] + red[t+64] + red[t+128] + red[t+192]) * (1.0f/1024.0f);
}

// ============ z = fbar @ Wo + bo ============
__global__ __launch_bounds__(256) void z_kernel(
    const float* __restrict__ Wo, const float* __restrict__ bo_,
    float* __restrict__ z)
{
    int n = blockIdx.x * 256 + threadIdx.x;
    int b = blockIdx.y;
    const float* f = g_fbar + b*1024;
    float acc = bo_[n];
    #pragma unroll 4
    for (int k = 0; k < 1024; k++) acc = fmaf(f[k], Wo[(size_t)k*1024 + n], acc);
    z[(size_t)b*1024 + n] = acc;
}

// =================================================================
extern "C" void kernel_launch(void* const* d_in, const int* in_sizes, int n_in,
                              void* d_out, int out_size)
{
    const float* x   = (const float*)d_in[0];
    const float* Wq  = (const float*)d_in[1];
    const float* bq  = (const float*)d_in[2];
    const float* Wk  = (const float*)d_in[3];
    const float* bk  = (const float*)d_in[4];
    const float* Wv  = (const float*)d_in[5];
    const float* bv  = (const float*)d_in[6];
    const float* Wg  = (const float*)d_in[7];
    const float* bg  = (const float*)d_in[8];
    const float* Wo  = (const float*)d_in[9];
    const float* bo  = (const float*)d_in[10];
    const float* Wu1 = (const float*)d_in[11];
    const float* bu1 = (const float*)d_in[12];
    const float* Wu2 = (const float*)d_in[13];
    const float* bu2 = (const float*)d_in[14];

    float* out       = (float*)d_out;
    float* z_out     = out;
    float* attn_out  = out + 8192;
    float* sigma_out = out + 8192 + (size_t)Bq*NHq*Mq*Mq;

    cudaFuncSetAttribute(attn_kernel,
        cudaFuncAttributeMaxDynamicSharedMemorySize, ATTN_SMEM_BYTES);
    cudaFuncSetAttribute(proj_mma_kernel,
        cudaFuncAttributeMaxDynamicSharedMemorySize, GEMM_SMEM);
    cudaFuncSetAttribute(sigma_mma_kernel,
        cudaFuncAttributeMaxDynamicSharedMemorySize, GEMM_SMEM);

    splitx_kernel<<<8192, 256>>>(x);
    tsplitw_kernel<<<dim3(32, 32, 5), 256>>>(Wq, Wk, Wv, Wg, Wu1);
    sigma_mma_kernel<<<64, 512, GEMM_SMEM>>>(bu1, Wu2, bu2, sigma_out);
    proj_mma_kernel<<<dim3(4, 64, 4), 512, GEMM_SMEM>>>(bq, bk, bv, bg);
    attn_kernel<<<dim3(32, 16, 8), 256, ATTN_SMEM_BYTES>>>(sigma_out, attn_out);
    mean_kernel<<<128, 256>>>();
    z_kernel<<<dim3(4, 8), 256>>>(Wo, bo, z_out);
}

// round 11
// speedup vs baseline: 2.0035x; 1.4265x over previous
#include <cuda_runtime.h>
#include <cuda_bf16.h>
#include <math.h>
#include <stdint.h>

#define Bq  8
#define Mq  1024
#define Hq  1024
#define NHq 16
#define HDq 64

// -------- scratch (device globals: no allocations allowed) --------
__device__ float g_G[Bq*NHq*Mq*HDq];
__device__ float g_ctx[Bq*NHq*Mq*HDq];
__device__ float g_fbar[Bq*Hq];

__device__ __nv_bfloat16 g_Qhi[Bq*NHq*Mq*HDq];
__device__ __nv_bfloat16 g_Qlo[Bq*NHq*Mq*HDq];
__device__ __nv_bfloat16 g_Khi[Bq*NHq*Mq*HDq];
__device__ __nv_bfloat16 g_Klo[Bq*NHq*Mq*HDq];
__device__ __nv_bfloat16 g_Vhi[Bq*NHq*Mq*HDq];
__device__ __nv_bfloat16 g_Vlo[Bq*NHq*Mq*HDq];
__device__ __nv_bfloat16 g_Vthi[Bq*NHq*HDq*Mq];   // [bh][d][n]
__device__ __nv_bfloat16 g_Vtlo[Bq*NHq*HDq*Mq];

// bf16 hi/lo split GEMM operands
__device__ __nv_bfloat16 g_Xhi[Bq*Mq*Hq];
__device__ __nv_bfloat16 g_Xlo[Bq*Mq*Hq];
__device__ __nv_bfloat16 g_Whi[4*Hq*Hq];      // transposed [n][k]
__device__ __nv_bfloat16 g_Wlo[4*Hq*Hq];
__device__ __nv_bfloat16 g_U1hi[256*Hq];      // transposed [n][k]
__device__ __nv_bfloat16 g_U1lo[256*Hq];

extern __shared__ char s_dyn[];

// ================= helpers =================
__device__ __forceinline__ uint32_t smem_u32(const void* p) {
    uint32_t a;
    asm("{ .reg .u64 t; cvta.to.shared.u64 t, %1; cvt.u32.u64 %0, t; }"
        : "=r"(a) : "l"(p));
    return a;
}
__device__ __forceinline__ void ldsm4(uint32_t* r, uint32_t addr) {
    asm volatile("ldmatrix.sync.aligned.m8n8.x4.shared.b16 {%0,%1,%2,%3}, [%4];"
        : "=r"(r[0]), "=r"(r[1]), "=r"(r[2]), "=r"(r[3]) : "r"(addr));
}
__device__ __forceinline__ void mma16816(float* d, const uint32_t* a, const uint32_t* b) {
    asm volatile("mma.sync.aligned.m16n8k16.row.col.f32.bf16.bf16.f32 "
        "{%0,%1,%2,%3}, {%4,%5,%6,%7}, {%8,%9}, {%0,%1,%2,%3};"
        : "+f"(d[0]), "+f"(d[1]), "+f"(d[2]), "+f"(d[3])
        : "r"(a[0]), "r"(a[1]), "r"(a[2]), "r"(a[3]), "r"(b[0]), "r"(b[1]));
}
__device__ __forceinline__ uint32_t packbf2(float e0, float e1) {
    uint32_t r;
    asm("cvt.rn.bf16x2.f32 %0, %1, %2;" : "=r"(r) : "f"(e1), "f"(e0));
    return r;
}
__device__ __forceinline__ float bflof(float v) {
    return __bfloat162float(__float2bfloat16(v));
}

// ================= prep: split X into bf16 hi/lo =================
__global__ __launch_bounds__(256) void splitx_kernel(const float* __restrict__ x)
{
    size_t i = ((size_t)blockIdx.x * 256 + threadIdx.x) * 4;
    float4 v = *(const float4*)(x + i);
    __nv_bfloat16 h0 = __float2bfloat16(v.x);
    __nv_bfloat16 h1 = __float2bfloat16(v.y);
    __nv_bfloat16 h2 = __float2bfloat16(v.z);
    __nv_bfloat16 h3 = __float2bfloat16(v.w);
    __nv_bfloat16 l0 = __float2bfloat16(v.x - __bfloat162float(h0));
    __nv_bfloat16 l1 = __float2bfloat16(v.y - __bfloat162float(h1));
    __nv_bfloat16 l2 = __float2bfloat16(v.z - __bfloat162float(h2));
    __nv_bfloat16 l3 = __float2bfloat16(v.w - __bfloat162float(h3));
    *(__nv_bfloat162*)(g_Xhi + i)     = __nv_bfloat162(h0, h1);
    *(__nv_bfloat162*)(g_Xhi + i + 2) = __nv_bfloat162(h2, h3);
    *(__nv_bfloat162*)(g_Xlo + i)     = __nv_bfloat162(l0, l1);
    *(__nv_bfloat162*)(g_Xlo + i + 2) = __nv_bfloat162(l2, l3);
}

// ============ prep: transpose + split W's ([K,N] -> [N,K] bf16 hi/lo) ============
__global__ __launch_bounds__(256) void tsplitw_kernel(
    const float* __restrict__ Wq, const float* __restrict__ Wk,
    const float* __restrict__ Wv, const float* __restrict__ Wg,
    const float* __restrict__ Wu1)
{
    __shared__ float tile[32][33];
    int z = blockIdx.z;
    const float* W; __nv_bfloat16 *oh, *ol; int N;
    if (z < 4) {
        W = (z == 0 ? Wq : z == 1 ? Wk : z == 2 ? Wv : Wg); N = 1024;
        oh = g_Whi + (size_t)z * 1024 * 1024; ol = g_Wlo + (size_t)z * 1024 * 1024;
    } else {
        W = Wu1; N = 256; oh = g_U1hi; ol = g_U1lo;
    }
    int kb = blockIdx.x * 32, nb = blockIdx.y * 32;
    if (nb >= N) return;
    int t = threadIdx.x, tx = t & 31, ty = t >> 5;
    #pragma unroll
    for (int i = 0; i < 4; i++)
        tile[ty + 8*i][tx] = W[(size_t)(kb + ty + 8*i) * N + nb + tx];
    __syncthreads();
    #pragma unroll
    for (int i = 0; i < 4; i++) {
        float v = tile[tx][ty + 8*i];
        __nv_bfloat16 h = __float2bfloat16(v);
        __nv_bfloat16 l = __float2bfloat16(v - __bfloat162float(h));
        size_t oidx = (size_t)(nb + ty + 8*i) * 1024 + kb + tx;
        oh[oidx] = h; ol[oidx] = l;
    }
}

// ============ prep: transpose V hi/lo to [bh][d][n] ============
__global__ __launch_bounds__(256) void transv_kernel()
{
    __shared__ __nv_bfloat16 th[64][72];
    __shared__ __nv_bfloat16 tl[64][72];
    int bh = blockIdx.y;
    int nb = blockIdx.x * 64;
    const __nv_bfloat16* sh = g_Vhi + ((size_t)bh*1024 + nb)*64;
    const __nv_bfloat16* sl = g_Vlo + ((size_t)bh*1024 + nb)*64;
    int t = threadIdx.x;
    int r = t >> 2, cseg = (t & 3)*16;
    *(uint4*)&th[r][cseg]     = *(const uint4*)(sh + (size_t)r*64 + cseg);
    *(uint4*)&th[r][cseg + 8] = *(const uint4*)(sh + (size_t)r*64 + cseg + 8);
    *(uint4*)&tl[r][cseg]     = *(const uint4*)(sl + (size_t)r*64 + cseg);
    *(uint4*)&tl[r][cseg + 8] = *(const uint4*)(sl + (size_t)r*64 + cseg + 8);
    __syncthreads();
    int d = t >> 2, nseg = (t & 3)*16;
    __nv_bfloat16 vh[16], vl[16];
    #pragma unroll
    for (int j = 0; j < 16; j++) { vh[j] = th[nseg + j][d]; vl[j] = tl[nseg + j][d]; }
    __nv_bfloat16* oh = g_Vthi + (size_t)bh*65536 + (size_t)d*1024 + nb + nseg;
    __nv_bfloat16* ol = g_Vtlo + (size_t)bh*65536 + (size_t)d*1024 + nb + nseg;
    *(uint4*)(oh)     = *(uint4*)&vh[0];
    *(uint4*)(oh + 8) = *(uint4*)&vh[8];
    *(uint4*)(ol)     = *(uint4*)&vl[0];
    *(uint4*)(ol + 8) = *(uint4*)&vl[8];
}

// ================= mma.sync GEMM core (proj/sigma) =================
#define ASTR 40
#define BSTR 40
#define A_ELE (128*ASTR)
#define B_ELE (256*BSTR)
#define BUF_ELE (2*A_ELE + 2*B_ELE)
#define GEMM_SMEM (2*BUF_ELE*2)

__device__ __forceinline__ void mma_gemm_main(
    const __nv_bfloat16* __restrict__ Ah, const __nv_bfloat16* __restrict__ Al,
    const __nv_bfloat16* __restrict__ Bh, const __nv_bfloat16* __restrict__ Bl,
    int mb, int nb, float acc[2][8][4])
{
    __nv_bfloat16* sm = (__nv_bfloat16*)s_dyn;
    const uint32_t smb = smem_u32(sm);
    const int t = threadIdx.x, lane = t & 31, wid = t >> 5;
    const int wm = wid & 3, wn = wid >> 2;

    const int aoff = (wm*32 + (lane & 15))*ASTR + ((lane >> 4) << 3);
    const int boff = (wn*64 + (lane & 7) + ((lane >> 4) << 3))*BSTR
                   + (((lane >> 3) & 1) << 3);

    const int arow = t >> 2;
    const int aseg = (t & 3) * 8;

    const __nv_bfloat16* pAh = Ah + (size_t)(mb + arow)*1024 + aseg;
    const __nv_bfloat16* pAl = Al + (size_t)(mb + arow)*1024 + aseg;
    const __nv_bfloat16* pB0h = Bh + (size_t)(nb + arow)*1024 + aseg;
    const __nv_bfloat16* pB1h = Bh + (size_t)(nb + arow + 128)*1024 + aseg;
    const __nv_bfloat16* pB0l = Bl + (size_t)(nb + arow)*1024 + aseg;
    const __nv_bfloat16* pB1l = Bl + (size_t)(nb + arow + 128)*1024 + aseg;

    const int stA = arow*ASTR + aseg;
    const int stB0 = arow*BSTR + aseg;
    const int stB1 = (arow + 128)*BSTR + aseg;

    uint4 ra_h, ra_l, rb0h, rb1h, rb0l, rb1l;
    ra_h = *(const uint4*)(pAh);  ra_l = *(const uint4*)(pAl);
    rb0h = *(const uint4*)(pB0h); rb1h = *(const uint4*)(pB1h);
    rb0l = *(const uint4*)(pB0l); rb1l = *(const uint4*)(pB1l);

    for (int c = 0; c < 32; c++) {
        const int bo = (c & 1) * BUF_ELE;
        *(uint4*)(sm + bo + stA)                    = ra_h;
        *(uint4*)(sm + bo + A_ELE + stA)            = ra_l;
        *(uint4*)(sm + bo + 2*A_ELE + stB0)         = rb0h;
        *(uint4*)(sm + bo + 2*A_ELE + stB1)         = rb1h;
        *(uint4*)(sm + bo + 2*A_ELE + B_ELE + stB0) = rb0l;
        *(uint4*)(sm + bo + 2*A_ELE + B_ELE + stB1) = rb1l;
        __syncthreads();
        if (c < 31) {
            int kb = (c + 1) * 32;
            ra_h = *(const uint4*)(pAh + kb);  ra_l = *(const uint4*)(pAl + kb);
            rb0h = *(const uint4*)(pB0h + kb); rb1h = *(const uint4*)(pB1h + kb);
            rb0l = *(const uint4*)(pB0l + kb); rb1l = *(const uint4*)(pB1l + kb);
        }
        #pragma unroll
        for (int ks = 0; ks < 2; ks++) {
            const int koff = ks * 16;
            uint32_t ah[2][4], al2[2][4], bhf[4][4], blf[4][4];
            #pragma unroll
            for (int mi = 0; mi < 2; mi++) {
                uint32_t ad = smb + (uint32_t)(bo + aoff + mi*16*ASTR + koff) * 2;
                ldsm4(ah[mi], ad);
                ldsm4(al2[mi], ad + A_ELE*2);
            }
            #pragma unroll
            for (int n2 = 0; n2 < 4; n2++) {
                uint32_t bd = smb + (uint32_t)(bo + 2*A_ELE + boff + n2*16*BSTR + koff) * 2;
                ldsm4(bhf[n2], bd);
                ldsm4(blf[n2], bd + B_ELE*2);
            }
            #pragma unroll
            for (int mi = 0; mi < 2; mi++)
                #pragma unroll
                for (int ni = 0; ni < 8; ni++)
                    mma16816(acc[mi][ni], ah[mi], &bhf[ni >> 1][(ni & 1) * 2]);
            #pragma unroll
            for (int mi = 0; mi < 2; mi++)
                #pragma unroll
                for (int ni = 0; ni < 8; ni++)
                    mma16816(acc[mi][ni], ah[mi], &blf[ni >> 1][(ni & 1) * 2]);
            #pragma unroll
            for (int mi = 0; mi < 2; mi++)
                #pragma unroll
                for (int ni = 0; ni < 8; ni++)
                    mma16816(acc[mi][ni], al2[mi], &bhf[ni >> 1][(ni & 1) * 2]);
        }
    }
}

// ================= projections via mma =================
// Outputs: Q,K,V -> bf16 hi/lo; G -> fp32 (sigmoid)
__global__ __launch_bounds__(512) void proj_mma_kernel(
    const float* __restrict__ bq_, const float* __restrict__ bk_,
    const float* __restrict__ bv_, const float* __restrict__ bg_)
{
    __shared__ float bias_s[256];
    int t = threadIdx.x, lane = t & 31, wid = t >> 5;
    int wn = wid >> 2, wm = wid & 3;
    int mb = blockIdx.y * 128;
    int nb = blockIdx.x * 256;
    int wsel = blockIdx.z;
    const __nv_bfloat16* Bh = g_Whi + (size_t)wsel * 1024 * 1024;
    const __nv_bfloat16* Bl = g_Wlo + (size_t)wsel * 1024 * 1024;
    const float* bias = wsel == 0 ? bq_ : wsel == 1 ? bk_ : wsel == 2 ? bv_ : bg_;

    if (t < 256) bias_s[t] = bias[nb + t];
    __syncthreads();

    float acc[2][8][4];
    #pragma unroll
    for (int mi = 0; mi < 2; mi++)
        #pragma unroll
        for (int ni = 0; ni < 8; ni++)
            #pragma unroll
            for (int j = 0; j < 4; j++) acc[mi][ni][j] = 0.f;

    mma_gemm_main(g_Xhi, g_Xlo, Bh, Bl, mb, nb, acc);

    int b = mb >> 10, mloc = mb & 1023;
    int hh = (nb >> 6) + wn;
    size_t base = ((size_t)(b*NHq + hh)*Mq + mloc)*HDq;
    int r0 = wm*32 + (lane >> 2);
    int c0 = (lane & 3) * 2;

    if (wsel == 3) {
        float* op = g_G + base;
        #pragma unroll
        for (int mi = 0; mi < 2; mi++) {
            #pragma unroll
            for (int ni = 0; ni < 8; ni++) {
                int col = ni*8 + c0;
                float b0 = bias_s[wn*64 + col], b1 = bias_s[wn*64 + col + 1];
                float v0 = 1.f/(1.f + __expf(-(acc[mi][ni][0] + b0)));
                float v1 = 1.f/(1.f + __expf(-(acc[mi][ni][1] + b1)));
                float v2 = 1.f/(1.f + __expf(-(acc[mi][ni][2] + b0)));
                float v3 = 1.f/(1.f + __expf(-(acc[mi][ni][3] + b1)));
                int row = r0 + mi*16;
                *(float2*)(op + (size_t)row*64 + col)     = make_float2(v0, v1);
                *(float2*)(op + (size_t)(row+8)*64 + col) = make_float2(v2, v3);
            }
        }
    } else {
        __nv_bfloat16* Hi = wsel == 0 ? g_Qhi : wsel == 1 ? g_Khi : g_Vhi;
        __nv_bfloat16* Lo = wsel == 0 ? g_Qlo : wsel == 1 ? g_Klo : g_Vlo;
        #pragma unroll
        for (int mi = 0; mi < 2; mi++) {
            #pragma unroll
            for (int ni = 0; ni < 8; ni++) {
                int col = ni*8 + c0;
                float b0 = bias_s[wn*64 + col], b1 = bias_s[wn*64 + col + 1];
                float v0 = acc[mi][ni][0] + b0, v1 = acc[mi][ni][1] + b1;
                float v2 = acc[mi][ni][2] + b0, v3 = acc[mi][ni][3] + b1;
                int row = r0 + mi*16;
                *(uint32_t*)(Hi + base + (size_t)row*64 + col)     = packbf2(v0, v1);
                *(uint32_t*)(Hi + base + (size_t)(row+8)*64 + col) = packbf2(v2, v3);
                float l0 = v0 - bflof(v0), l1 = v1 - bflof(v1);
                float l2 = v2 - bflof(v2), l3 = v3 - bflof(v3);
                *(uint32_t*)(Lo + base + (size_t)row*64 + col)     = packbf2(l0, l1);
                *(uint32_t*)(Lo + base + (size_t)(row+8)*64 + col) = packbf2(l2, l3);
            }
        }
    }
}

// ================= sigma via mma (N=256, fused epilogue) =================
__global__ __launch_bounds__(512) void sigma_mma_kernel(
    const float* __restrict__ bu1, const float* __restrict__ Wu2,
    const float* __restrict__ bu2, float* __restrict__ sigma_out)
{
    __shared__ float bu1_s[256], wu2_s[256];
    __shared__ float red[128][4];
    int t = threadIdx.x, lane = t & 31, wid = t >> 5;
    int wm = wid & 3, wn = wid >> 2;
    int mb = blockIdx.x * 128;

    if (t < 256) { bu1_s[t] = bu1[t]; wu2_s[t] = Wu2[t]; }
    __syncthreads();

    float acc[2][8][4];
    #pragma unroll
    for (int mi = 0; mi < 2; mi++)
        #pragma unroll
        for (int ni = 0; ni < 8; ni++)
            #pragma unroll
            for (int j = 0; j < 4; j++) acc[mi][ni][j] = 0.f;

    mma_gemm_main(g_Xhi, g_Xlo, g_U1hi, g_U1lo, mb, 0, acc);

    int c0 = (lane & 3) * 2;
    float p[2][2] = {{0.f,0.f},{0.f,0.f}};
    #pragma unroll
    for (int mi = 0; mi < 2; mi++) {
        #pragma unroll
        for (int ni = 0; ni < 8; ni++) {
            int col = wn*64 + ni*8 + c0;
            float w0 = wu2_s[col], w1 = wu2_s[col+1];
            float a0 = fmaxf(acc[mi][ni][0] + bu1_s[col],   0.f);
            float a1 = fmaxf(acc[mi][ni][1] + bu1_s[col+1], 0.f);
            float a2 = fmaxf(acc[mi][ni][2] + bu1_s[col],   0.f);
            float a3 = fmaxf(acc[mi][ni][3] + bu1_s[col+1], 0.f);
            p[mi][0] += a0*w0 + a1*w1;
            p[mi][1] += a2*w0 + a3*w1;
        }
    }
    #pragma unroll
    for (int mi = 0; mi < 2; mi++)
        #pragma unroll
        for (int j = 0; j < 2; j++) {
            p[mi][j] += __shfl_xor_sync(0xFFFFFFFF, p[mi][j], 1);
            p[mi][j] += __shfl_xor_sync(0xFFFFFFFF, p[mi][j], 2);
        }
    if ((lane & 3) == 0) {
        #pragma unroll
        for (int mi = 0; mi < 2; mi++)
            #pragma unroll
            for (int j = 0; j < 2; j++)
                red[wm*32 + mi*16 + j*8 + (lane >> 2)][wn] = p[mi][j];
    }
    __syncthreads();
    if (t < 128) {
        float zv = red[t][0] + red[t][1] + red[t][2] + red[t][3] + bu2[0];
        float sp = (zv > 20.f) ? zv : log1pf(expf(zv));
        sigma_out[mb + t] = sp + 1e-6f;
    }
}

// =================================================================
// Tensorized attention per (b, h, 32-row m-tile)
// =================================================================
#define SSTRF 1036
#define ROWB  4144
#define PLOFF 2080
#define KSTR  72
#define VSTR  264
#define CSTR  68
#define KH_OFF  132608
#define KL_OFF  169472
#define QH_OFF  206336
#define QL_OFF  210944
#define INV_OFF 215552
#define RF_OFF  219648
#define ATTN2_SMEM 219776

__global__ __launch_bounds__(256) void attn2_kernel(
    const float* __restrict__ sigma, float* __restrict__ attn_out)
{
    char* smb = s_dyn;
    float* Ss = (float*)smb;
    __nv_bfloat16* Kh = (__nv_bfloat16*)(smb + KH_OFF);
    __nv_bfloat16* Kl = (__nv_bfloat16*)(smb + KL_OFF);
    __nv_bfloat16* Qh = (__nv_bfloat16*)(smb + QH_OFF);
    __nv_bfloat16* Ql = (__nv_bfloat16*)(smb + QL_OFF);
    float* invn   = (float*)(smb + INV_OFF);
    float* rowfac = (float*)(smb + RF_OFF);
    __shared__ float red[256];
    __shared__ float rowmax[32];
    __shared__ float rinv_s[32];

    int t = threadIdx.x, lane = t & 31, wid = t >> 5;
    int m0 = blockIdx.x * 32;
    int bh = blockIdx.z * NHq + blockIdx.y;
    const __nv_bfloat16* Qhg = g_Qhi + (size_t)bh*Mq*HDq;
    const __nv_bfloat16* Qlg = g_Qlo + (size_t)bh*Mq*HDq;
    const __nv_bfloat16* Khg = g_Khi + (size_t)bh*Mq*HDq;
    const __nv_bfloat16* Klg = g_Klo + (size_t)bh*Mq*HDq;
    const __nv_bfloat16* Vth = g_Vthi + (size_t)bh*HDq*Mq;
    const __nv_bfloat16* Vtl = g_Vtlo + (size_t)bh*HDq*Mq;
    const float* Gg = g_G + (size_t)bh*Mq*HDq;
    float*       Cg = g_ctx + (size_t)bh*Mq*HDq;
    const float* sigb = sigma + blockIdx.z*Mq;

    for (int i = t; i < 1024; i += 256) invn[i] = 1.0f / sigb[i];
    if (t < 32) rowfac[t] = 0.125f / sigb[m0 + t];

    // stage Q tile (32x64 hi/lo)
    {
        int r = t >> 3, seg = t & 7;
        *(uint4*)(Qh + r*KSTR + seg*8) = *(const uint4*)(Qhg + (size_t)(m0 + r)*64 + seg*8);
        *(uint4*)(Ql + r*KSTR + seg*8) = *(const uint4*)(Qlg + (size_t)(m0 + r)*64 + seg*8);
    }

    const int mh = wid >> 2;         // 0..1 (m half)
    const int nw = wid & 3;          // 0..3 (n slice)
    const uint32_t qh_base = smem_u32(Qh) + (uint32_t)((mh*16 + (lane & 15))*KSTR + ((lane >> 4) << 3)) * 2;
    const uint32_t ql_base = smem_u32(Ql) + (uint32_t)((mh*16 + (lane & 15))*KSTR + ((lane >> 4) << 3)) * 2;
    // B-operand lane pattern — EXACTLY the proj convention:
    //   row term: (lane&7) + ((lane>>4)<<3), col term: ((lane>>3)&1)<<3
    const uint32_t koff_lane = (uint32_t)(((lane & 7) + ((lane >> 4) << 3))*KSTR
                              + (((lane >> 3) & 1) << 3)) * 2;
    const int r0 = mh*16 + (lane >> 2);
    const int c0 = (lane & 3) * 2;

    // ---- S = scaled Q Kt (hi/lo 3-pass mma) ----
    for (int nc = 0; nc < 4; nc++) {
        __syncthreads();
        #pragma unroll
        for (int p = 0; p < 8; p++) {
            int i = p*256 + t;
            int r = i >> 3, seg = i & 7;
            *(uint4*)(Kh + r*KSTR + seg*8) = *(const uint4*)(Khg + (size_t)(nc*256 + r)*64 + seg*8);
            *(uint4*)(Kl + r*KSTR + seg*8) = *(const uint4*)(Klg + (size_t)(nc*256 + r)*64 + seg*8);
        }
        __syncthreads();
        float acc[8][4];
        #pragma unroll
        for (int ni = 0; ni < 8; ni++)
            #pragma unroll
            for (int j = 0; j < 4; j++) acc[ni][j] = 0.f;

        #pragma unroll
        for (int ks = 0; ks < 4; ks++) {
            uint32_t ah[4], al[4];
            ldsm4(ah, qh_base + ks*32);
            ldsm4(al, ql_base + ks*32);
            uint32_t bh4[4][4], bl4[4][4];
            #pragma unroll
            for (int g = 0; g < 4; g++) {
                uint32_t kb = koff_lane + (uint32_t)((nw*64 + g*16)*KSTR)*2 + ks*32;
                ldsm4(bh4[g], smem_u32(Kh) + kb);
                ldsm4(bl4[g], smem_u32(Kl) + kb);
            }
            #pragma unroll
            for (int ni = 0; ni < 8; ni++) mma16816(acc[ni], ah, &bh4[ni >> 1][(ni & 1)*2]);
            #pragma unroll
            for (int ni = 0; ni < 8; ni++) mma16816(acc[ni], ah, &bl4[ni >> 1][(ni & 1)*2]);
            #pragma unroll
            for (int ni = 0; ni < 8; ni++) mma16816(acc[ni], al, &bh4[ni >> 1][(ni & 1)*2]);
        }
        float f0 = rowfac[r0], f1 = rowfac[r0 + 8];
        #pragma unroll
        for (int ni = 0; ni < 8; ni++) {
            int col = nc*256 + nw*64 + ni*8 + c0;
            float iv0 = invn[col], iv1 = invn[col + 1];
            *(float2*)&Ss[(size_t)r0*SSTRF + col]       = make_float2(acc[ni][0]*f0*iv0, acc[ni][1]*f0*iv1);
            *(float2*)&Ss[(size_t)(r0 + 8)*SSTRF + col] = make_float2(acc[ni][2]*f1*iv0, acc[ni][3]*f1*iv1);
        }
    }
    __syncthreads();

    // ---- softmax (8 threads per row) ----
    {
        int r = t >> 3;
        int q = t & 7;
        float* srow = Ss + (size_t)r*SSTRF;
        float mx = -1e30f;
        for (int c = q; c < 1024; c += 8) mx = fmaxf(mx, srow[c]);
        red[t] = mx;
        __syncthreads();
        if (q == 0) {
            float m = red[t];
            #pragma unroll
            for (int j = 1; j < 8; j++) m = fmaxf(m, red[t + j]);
            rowmax[r] = m;
        }
        __syncthreads();
        float rm = rowmax[r];
        float sum = 0.f;
        for (int c = q; c < 1024; c += 8) {
            float e = __expf(srow[c] - rm);
            srow[c] = e;
            sum += e;
        }
        red[t] = sum;
        __syncthreads();
        if (q == 0) {
            float s = red[t];
            #pragma unroll
            for (int j = 1; j < 8; j++) s += red[t + j];
            rinv_s[r] = 1.0f / s;
        }
        __syncthreads();
    }

    // ---- normalize + write attn + pack P hi/lo (bf16) in place ----
    {
        float* aout = attn_out + ((size_t)bh*Mq + m0) * 1024;
        #pragma unroll 1
        for (int r = 0; r < 32; r++) {
            float ri = rinv_s[r];
            float4 p = *(float4*)&Ss[(size_t)r*SSTRF + t*4];
            p.x *= ri; p.y *= ri; p.z *= ri; p.w *= ri;
            __syncthreads();   // all reads of row r done before overwrite
            *(float4*)&aout[(size_t)r*1024 + t*4] = p;
            float hx = bflof(p.x), hy = bflof(p.y), hz = bflof(p.z), hw = bflof(p.w);
            char* rb = smb + (size_t)r*ROWB;
            *(uint2*)(rb + 8*t) = make_uint2(packbf2(p.x, p.y), packbf2(p.z, p.w));
            *(uint2*)(rb + PLOFF + 8*t) =
                make_uint2(packbf2(p.x - hx, p.y - hy), packbf2(p.z - hz, p.w - hw));
        }
    }

    // ---- ctx = P @ Vt via mma (hi/lo 3-pass) ----
    float ctx[8][4];
    #pragma unroll
    for (int di = 0; di < 8; di++)
        #pragma unroll
        for (int j = 0; j < 4; j++) ctx[di][j] = 0.f;

    const uint32_t prow_base = smem_u32(smb) + (uint32_t)((mh*16 + (lane & 15))*ROWB)
                             + ((uint32_t)(lane >> 4) << 4);
    // B-operand lane pattern — proj convention (row: lane&7 + (lane>>4)<<3)
    const uint32_t vrow_lane = (uint32_t)((lane & 7) + ((lane >> 4) << 3));
    const uint32_t vh_base = smem_u32(Kh);
    const uint32_t vl_base = smem_u32(Kl);

    for (int nc = 0; nc < 4; nc++) {
        __syncthreads();
        {   // stage Vt chunk: 64 d-rows x 256 n-cols, hi+lo
            int d = t >> 2, cb = (t & 3) * 64;
            #pragma unroll
            for (int j = 0; j < 8; j++) {
                *(uint4*)(Kh + d*VSTR + cb + j*8) =
                    *(const uint4*)(Vth + (size_t)d*1024 + nc*256 + cb + j*8);
                *(uint4*)(Kl + d*VSTR + cb + j*8) =
                    *(const uint4*)(Vtl + (size_t)d*1024 + nc*256 + cb + j*8);
            }
        }
        __syncthreads();
        #pragma unroll
        for (int ks = 0; ks < 4; ks++) {
            uint32_t acolb = (uint32_t)(nc*256 + nw*64 + ks*16) * 2;
            uint32_t ah[4], al[4];
            ldsm4(ah, prow_base + acolb);
            ldsm4(al, prow_base + PLOFF + acolb);
            // column term carries the proj-style ((lane>>3)&1)<<3 k-half select
            uint32_t bcolb = (uint32_t)(nw*64 + ks*16 + (((lane >> 3) & 1) << 3)) * 2;
            uint32_t bvh[4][4], bvl[4][4];
            #pragma unroll
            for (int g = 0; g < 4; g++) {
                uint32_t boffb = (uint32_t)((g*16 + vrow_lane)*VSTR)*2 + bcolb;
                ldsm4(bvh[g], vh_base + boffb);
                ldsm4(bvl[g], vl_base + boffb);
            }
            #pragma unroll
            for (int di = 0; di < 8; di++) mma16816(ctx[di], ah, &bvh[di >> 1][(di & 1)*2]);
            #pragma unroll
            for (int di = 0; di < 8; di++) mma16816(ctx[di], ah, &bvl[di >> 1][(di & 1)*2]);
            #pragma unroll
            for (int di = 0; di < 8; di++) mma16816(ctx[di], al, &bvh[di >> 1][(di & 1)*2]);
        }
    }
    __syncthreads();

    // ---- reduce k-split partials, gate, store ----
    float* part = (float*)Kh;   // [4][32][CSTR]
    #pragma unroll
    for (int di = 0; di < 8; di++) {
        int c = di*8 + c0;
        *(float2*)&part[(nw*32 + r0)*CSTR + c]     = make_float2(ctx[di][0], ctx[di][1]);
        *(float2*)&part[(nw*32 + r0 + 8)*CSTR + c] = make_float2(ctx[di][2], ctx[di][3]);
    }
    __syncthreads();
    {
        int r = t >> 3, d0 = (t & 7) * 8;
        float v[8];
        #pragma unroll
        for (int j = 0; j < 8; j++)
            v[j] = part[r*CSTR + d0 + j] + part[(32 + r)*CSTR + d0 + j]
                 + part[(64 + r)*CSTR + d0 + j] + part[(96 + r)*CSTR + d0 + j];
        float4 g0 = *(const float4*)(Gg + (size_t)(m0 + r)*64 + d0);
        float4 g1 = *(const float4*)(Gg + (size_t)(m0 + r)*64 + d0 + 4);
        float4 o0 = make_float4(v[0]*g0.x, v[1]*g0.y, v[2]*g0.z, v[3]*g0.w);
        float4 o1 = make_float4(v[4]*g1.x, v[5]*g1.y, v[6]*g1.z, v[7]*g1.w);
        *(float4*)(Cg + (size_t)(m0 + r)*64 + d0)     = o0;
        *(float4*)(Cg + (size_t)(m0 + r)*64 + d0 + 4) = o1;
    }
}

// ============ mean over m: 1 block per (b,h) ============
__global__ __launch_bounds__(256) void mean_kernel()
{
    __shared__ float red[256];
    int bh = blockIdx.x;
    int t = threadIdx.x;
    int d = t & 63, grp = t >> 6;
    const float* p = g_ctx + (size_t)bh*Mq*HDq + grp*64 + d;
    float s = 0.f;
    #pragma unroll 8
    for (int m = 0; m < 256; m++) s += p[(size_t)m*256];
    red[t] = s;
    __syncthreads();
    if (t < 64)
        g_fbar[(size_t)bh*64 + d] =
            (red[t] + red[t+64] + red[t+128] + red[t+192]) * (1.0f/1024.0f);
}

// ============ z = fbar @ Wo + bo ============
__global__ __launch_bounds__(256) void z_kernel(
    const float* __restrict__ Wo, const float* __restrict__ bo_,
    float* __restrict__ z)
{
    int n = blockIdx.x * 256 + threadIdx.x;
    int b = blockIdx.y;
    const float* f = g_fbar + b*1024;
    float acc = bo_[n];
    #pragma unroll 4
    for (int k = 0; k < 1024; k++) acc = fmaf(f[k], Wo[(size_t)k*1024 + n], acc);
    z[(size_t)b*1024 + n] = acc;
}

// =================================================================
extern "C" void kernel_launch(void* const* d_in, const int* in_sizes, int n_in,
                              void* d_out, int out_size)
{
    const float* x   = (const float*)d_in[0];
    const float* Wq  = (const float*)d_in[1];
    const float* bq  = (const float*)d_in[2];
    const float* Wk  = (const float*)d_in[3];
    const float* bk  = (const float*)d_in[4];
    const float* Wv  = (const float*)d_in[5];
    const float* bv  = (const float*)d_in[6];
    const float* Wg  = (const float*)d_in[7];
    const float* bg  = (const float*)d_in[8];
    const float* Wo  = (const float*)d_in[9];
    const float* bo  = (const float*)d_in[10];
    const float* Wu1 = (const float*)d_in[11];
    const float* bu1 = (const float*)d_in[12];
    const float* Wu2 = (const float*)d_in[13];
    const float* bu2 = (const float*)d_in[14];

    float* out       = (float*)d_out;
    float* z_out     = out;
    float* attn_out  = out + 8192;
    float* sigma_out = out + 8192 + (size_t)Bq*NHq*Mq*Mq;

    cudaFuncSetAttribute(attn2_kernel,
        cudaFuncAttributeMaxDynamicSharedMemorySize, ATTN2_SMEM);
    cudaFuncSetAttribute(proj_mma_kernel,
        cudaFuncAttributeMaxDynamicSharedMemorySize, GEMM_SMEM);
    cudaFuncSetAttribute(sigma_mma_kernel,
        cudaFuncAttributeMaxDynamicSharedMemorySize, GEMM_SMEM);

    splitx_kernel<<<8192, 256>>>(x);
    tsplitw_kernel<<<dim3(32, 32, 5), 256>>>(Wq, Wk, Wv, Wg, Wu1);
    sigma_mma_kernel<<<64, 512, GEMM_SMEM>>>(bu1, Wu2, bu2, sigma_out);
    proj_mma_kernel<<<dim3(4, 64, 4), 512, GEMM_SMEM>>>(bq, bk, bv, bg);
    transv_kernel<<<dim3(16, 128), 256>>>();
    attn2_kernel<<<dim3(32, 16, 8), 256, ATTN2_SMEM>>>(sigma_out, attn_out);
    mean_kernel<<<128, 256>>>();
    z_kernel<<<dim3(4, 8), 256>>>(Wo, bo, z_out);
}

// round 12
// speedup vs baseline: 2.3778x; 1.1868x over previous
#include <cuda_runtime.h>
#include <cuda_bf16.h>
#include <math.h>
#include <stdint.h>

#define Bq  8
#define Mq  1024
#define Hq  1024
#define NHq 16
#define HDq 64

// -------- scratch (device globals: no allocations allowed) --------
__device__ float g_G[Bq*NHq*Mq*HDq];
__device__ float g_ctx[Bq*NHq*Mq*HDq];
__device__ float g_fbar[Bq*Hq];

__device__ __nv_bfloat16 g_Qhi[Bq*NHq*Mq*HDq];
__device__ __nv_bfloat16 g_Qlo[Bq*NHq*Mq*HDq];
__device__ __nv_bfloat16 g_Khi[Bq*NHq*Mq*HDq];
__device__ __nv_bfloat16 g_Klo[Bq*NHq*Mq*HDq];
__device__ __nv_bfloat16 g_Vhi[Bq*NHq*Mq*HDq];
__device__ __nv_bfloat16 g_Vlo[Bq*NHq*Mq*HDq];
__device__ __nv_bfloat16 g_Vthi[Bq*NHq*HDq*Mq];   // [bh][d][n]
__device__ __nv_bfloat16 g_Vtlo[Bq*NHq*HDq*Mq];

// bf16 hi/lo split GEMM operands
__device__ __nv_bfloat16 g_Xhi[Bq*Mq*Hq];
__device__ __nv_bfloat16 g_Xlo[Bq*Mq*Hq];
__device__ __nv_bfloat16 g_Whi[4*Hq*Hq];      // transposed [n][k]
__device__ __nv_bfloat16 g_Wlo[4*Hq*Hq];
__device__ __nv_bfloat16 g_U1hi[256*Hq];      // transposed [n][k]
__device__ __nv_bfloat16 g_U1lo[256*Hq];

extern __shared__ char s_dyn[];

// ================= helpers =================
__device__ __forceinline__ uint32_t smem_u32(const void* p) {
    uint32_t a;
    asm("{ .reg .u64 t; cvta.to.shared.u64 t, %1; cvt.u32.u64 %0, t; }"
        : "=r"(a) : "l"(p));
    return a;
}
__device__ __forceinline__ void ldsm4(uint32_t* r, uint32_t addr) {
    asm volatile("ldmatrix.sync.aligned.m8n8.x4.shared.b16 {%0,%1,%2,%3}, [%4];"
        : "=r"(r[0]), "=r"(r[1]), "=r"(r[2]), "=r"(r[3]) : "r"(addr));
}
__device__ __forceinline__ void mma16816(float* d, const uint32_t* a, const uint32_t* b) {
    asm volatile("mma.sync.aligned.m16n8k16.row.col.f32.bf16.bf16.f32 "
        "{%0,%1,%2,%3}, {%4,%5,%6,%7}, {%8,%9}, {%0,%1,%2,%3};"
        : "+f"(d[0]), "+f"(d[1]), "+f"(d[2]), "+f"(d[3])
        : "r"(a[0]), "r"(a[1]), "r"(a[2]), "r"(a[3]), "r"(b[0]), "r"(b[1]));
}
__device__ __forceinline__ uint32_t packbf2(float e0, float e1) {
    uint32_t r;
    asm("cvt.rn.bf16x2.f32 %0, %1, %2;" : "=r"(r) : "f"(e1), "f"(e0));
    return r;
}
__device__ __forceinline__ float bflof(float v) {
    return __bfloat162float(__float2bfloat16(v));
}

// ================= prep: split X into bf16 hi/lo =================
__global__ __launch_bounds__(256) void splitx_kernel(const float* __restrict__ x)
{
    size_t i = ((size_t)blockIdx.x * 256 + threadIdx.x) * 4;
    float4 v = *(const float4*)(x + i);
    __nv_bfloat16 h0 = __float2bfloat16(v.x);
    __nv_bfloat16 h1 = __float2bfloat16(v.y);
    __nv_bfloat16 h2 = __float2bfloat16(v.z);
    __nv_bfloat16 h3 = __float2bfloat16(v.w);
    __nv_bfloat16 l0 = __float2bfloat16(v.x - __bfloat162float(h0));
    __nv_bfloat16 l1 = __float2bfloat16(v.y - __bfloat162float(h1));
    __nv_bfloat16 l2 = __float2bfloat16(v.z - __bfloat162float(h2));
    __nv_bfloat16 l3 = __float2bfloat16(v.w - __bfloat162float(h3));
    *(__nv_bfloat162*)(g_Xhi + i)     = __nv_bfloat162(h0, h1);
    *(__nv_bfloat162*)(g_Xhi + i + 2) = __nv_bfloat162(h2, h3);
    *(__nv_bfloat162*)(g_Xlo + i)     = __nv_bfloat162(l0, l1);
    *(__nv_bfloat162*)(g_Xlo + i + 2) = __nv_bfloat162(l2, l3);
}

// ============ prep: transpose + split W's ([K,N] -> [N,K] bf16 hi/lo) ============
__global__ __launch_bounds__(256) void tsplitw_kernel(
    const float* __restrict__ Wq, const float* __restrict__ Wk,
    const float* __restrict__ Wv, const float* __restrict__ Wg,
    const float* __restrict__ Wu1)
{
    __shared__ float tile[32][33];
    int z = blockIdx.z;
    const float* W; __nv_bfloat16 *oh, *ol; int N;
    if (z < 4) {
        W = (z == 0 ? Wq : z == 1 ? Wk : z == 2 ? Wv : Wg); N = 1024;
        oh = g_Whi + (size_t)z * 1024 * 1024; ol = g_Wlo + (size_t)z * 1024 * 1024;
    } else {
        W = Wu1; N = 256; oh = g_U1hi; ol = g_U1lo;
    }
    int kb = blockIdx.x * 32, nb = blockIdx.y * 32;
    if (nb >= N) return;
    int t = threadIdx.x, tx = t & 31, ty = t >> 5;
    #pragma unroll
    for (int i = 0; i < 4; i++)
        tile[ty + 8*i][tx] = W[(size_t)(kb + ty + 8*i) * N + nb + tx];
    __syncthreads();
    #pragma unroll
    for (int i = 0; i < 4; i++) {
        float v = tile[tx][ty + 8*i];
        __nv_bfloat16 h = __float2bfloat16(v);
        __nv_bfloat16 l = __float2bfloat16(v - __bfloat162float(h));
        size_t oidx = (size_t)(nb + ty + 8*i) * 1024 + kb + tx;
        oh[oidx] = h; ol[oidx] = l;
    }
}

// ============ prep: transpose V hi/lo to [bh][d][n] ============
__global__ __launch_bounds__(256) void transv_kernel()
{
    __shared__ __nv_bfloat16 th[64][72];
    __shared__ __nv_bfloat16 tl[64][72];
    int bh = blockIdx.y;
    int nb = blockIdx.x * 64;
    const __nv_bfloat16* sh = g_Vhi + ((size_t)bh*1024 + nb)*64;
    const __nv_bfloat16* sl = g_Vlo + ((size_t)bh*1024 + nb)*64;
    int t = threadIdx.x;
    int r = t >> 2, cseg = (t & 3)*16;
    *(uint4*)&th[r][cseg]     = *(const uint4*)(sh + (size_t)r*64 + cseg);
    *(uint4*)&th[r][cseg + 8] = *(const uint4*)(sh + (size_t)r*64 + cseg + 8);
    *(uint4*)&tl[r][cseg]     = *(const uint4*)(sl + (size_t)r*64 + cseg);
    *(uint4*)&tl[r][cseg + 8] = *(const uint4*)(sl + (size_t)r*64 + cseg + 8);
    __syncthreads();
    int d = t >> 2, nseg = (t & 3)*16;
    __nv_bfloat16 vh[16], vl[16];
    #pragma unroll
    for (int j = 0; j < 16; j++) { vh[j] = th[nseg + j][d]; vl[j] = tl[nseg + j][d]; }
    __nv_bfloat16* oh = g_Vthi + (size_t)bh*65536 + (size_t)d*1024 + nb + nseg;
    __nv_bfloat16* ol = g_Vtlo + (size_t)bh*65536 + (size_t)d*1024 + nb + nseg;
    *(uint4*)(oh)     = *(uint4*)&vh[0];
    *(uint4*)(oh + 8) = *(uint4*)&vh[8];
    *(uint4*)(ol)     = *(uint4*)&vl[0];
    *(uint4*)(ol + 8) = *(uint4*)&vl[8];
}

// ================= mma.sync GEMM core (proj/sigma) =================
#define ASTR 40
#define BSTR 40
#define A_ELE (128*ASTR)
#define B_ELE (256*BSTR)
#define BUF_ELE (2*A_ELE + 2*B_ELE)
#define GEMM_SMEM (2*BUF_ELE*2)

__device__ __forceinline__ void mma_gemm_main(
    const __nv_bfloat16* __restrict__ Ah, const __nv_bfloat16* __restrict__ Al,
    const __nv_bfloat16* __restrict__ Bh, const __nv_bfloat16* __restrict__ Bl,
    int mb, int nb, float acc[2][8][4])
{
    __nv_bfloat16* sm = (__nv_bfloat16*)s_dyn;
    const uint32_t smb = smem_u32(sm);
    const int t = threadIdx.x, lane = t & 31, wid = t >> 5;
    const int wm = wid & 3, wn = wid >> 2;

    const int aoff = (wm*32 + (lane & 15))*ASTR + ((lane >> 4) << 3);
    const int boff = (wn*64 + (lane & 7) + ((lane >> 4) << 3))*BSTR
                   + (((lane >> 3) & 1) << 3);

    const int arow = t >> 2;
    const int aseg = (t & 3) * 8;

    const __nv_bfloat16* pAh = Ah + (size_t)(mb + arow)*1024 + aseg;
    const __nv_bfloat16* pAl = Al + (size_t)(mb + arow)*1024 + aseg;
    const __nv_bfloat16* pB0h = Bh + (size_t)(nb + arow)*1024 + aseg;
    const __nv_bfloat16* pB1h = Bh + (size_t)(nb + arow + 128)*1024 + aseg;
    const __nv_bfloat16* pB0l = Bl + (size_t)(nb + arow)*1024 + aseg;
    const __nv_bfloat16* pB1l = Bl + (size_t)(nb + arow + 128)*1024 + aseg;

    const int stA = arow*ASTR + aseg;
    const int stB0 = arow*BSTR + aseg;
    const int stB1 = (arow + 128)*BSTR + aseg;

    uint4 ra_h, ra_l, rb0h, rb1h, rb0l, rb1l;
    ra_h = *(const uint4*)(pAh);  ra_l = *(const uint4*)(pAl);
    rb0h = *(const uint4*)(pB0h); rb1h = *(const uint4*)(pB1h);
    rb0l = *(const uint4*)(pB0l); rb1l = *(const uint4*)(pB1l);

    for (int c = 0; c < 32; c++) {
        const int bo = (c & 1) * BUF_ELE;
        *(uint4*)(sm + bo + stA)                    = ra_h;
        *(uint4*)(sm + bo + A_ELE + stA)            = ra_l;
        *(uint4*)(sm + bo + 2*A_ELE + stB0)         = rb0h;
        *(uint4*)(sm + bo + 2*A_ELE + stB1)         = rb1h;
        *(uint4*)(sm + bo + 2*A_ELE + B_ELE + stB0) = rb0l;
        *(uint4*)(sm + bo + 2*A_ELE + B_ELE + stB1) = rb1l;
        __syncthreads();
        if (c < 31) {
            int kb = (c + 1) * 32;
            ra_h = *(const uint4*)(pAh + kb);  ra_l = *(const uint4*)(pAl + kb);
            rb0h = *(const uint4*)(pB0h + kb); rb1h = *(const uint4*)(pB1h + kb);
            rb0l = *(const uint4*)(pB0l + kb); rb1l = *(const uint4*)(pB1l + kb);
        }
        #pragma unroll
        for (int ks = 0; ks < 2; ks++) {
            const int koff = ks * 16;
            uint32_t ah[2][4], al2[2][4], bhf[4][4], blf[4][4];
            #pragma unroll
            for (int mi = 0; mi < 2; mi++) {
                uint32_t ad = smb + (uint32_t)(bo + aoff + mi*16*ASTR + koff) * 2;
                ldsm4(ah[mi], ad);
                ldsm4(al2[mi], ad + A_ELE*2);
            }
            #pragma unroll
            for (int n2 = 0; n2 < 4; n2++) {
                uint32_t bd = smb + (uint32_t)(bo + 2*A_ELE + boff + n2*16*BSTR + koff) * 2;
                ldsm4(bhf[n2], bd);
                ldsm4(blf[n2], bd + B_ELE*2);
            }
            #pragma unroll
            for (int mi = 0; mi < 2; mi++)
                #pragma unroll
                for (int ni = 0; ni < 8; ni++)
                    mma16816(acc[mi][ni], ah[mi], &bhf[ni >> 1][(ni & 1) * 2]);
            #pragma unroll
            for (int mi = 0; mi < 2; mi++)
                #pragma unroll
                for (int ni = 0; ni < 8; ni++)
                    mma16816(acc[mi][ni], ah[mi], &blf[ni >> 1][(ni & 1) * 2]);
            #pragma unroll
            for (int mi = 0; mi < 2; mi++)
                #pragma unroll
                for (int ni = 0; ni < 8; ni++)
                    mma16816(acc[mi][ni], al2[mi], &bhf[ni >> 1][(ni & 1) * 2]);
        }
    }
}

// ================= projections via mma =================
// Outputs: Q,K,V -> bf16 hi/lo; G -> fp32 (sigmoid)
__global__ __launch_bounds__(512) void proj_mma_kernel(
    const float* __restrict__ bq_, const float* __restrict__ bk_,
    const float* __restrict__ bv_, const float* __restrict__ bg_)
{
    __shared__ float bias_s[256];
    int t = threadIdx.x, lane = t & 31, wid = t >> 5;
    int wn = wid >> 2, wm = wid & 3;
    int mb = blockIdx.y * 128;
    int nb = blockIdx.x * 256;
    int wsel = blockIdx.z;
    const __nv_bfloat16* Bh = g_Whi + (size_t)wsel * 1024 * 1024;
    const __nv_bfloat16* Bl = g_Wlo + (size_t)wsel * 1024 * 1024;
    const float* bias = wsel == 0 ? bq_ : wsel == 1 ? bk_ : wsel == 2 ? bv_ : bg_;

    if (t < 256) bias_s[t] = bias[nb + t];
    __syncthreads();

    float acc[2][8][4];
    #pragma unroll
    for (int mi = 0; mi < 2; mi++)
        #pragma unroll
        for (int ni = 0; ni < 8; ni++)
            #pragma unroll
            for (int j = 0; j < 4; j++) acc[mi][ni][j] = 0.f;

    mma_gemm_main(g_Xhi, g_Xlo, Bh, Bl, mb, nb, acc);

    int b = mb >> 10, mloc = mb & 1023;
    int hh = (nb >> 6) + wn;
    size_t base = ((size_t)(b*NHq + hh)*Mq + mloc)*HDq;
    int r0 = wm*32 + (lane >> 2);
    int c0 = (lane & 3) * 2;

    if (wsel == 3) {
        float* op = g_G + base;
        #pragma unroll
        for (int mi = 0; mi < 2; mi++) {
            #pragma unroll
            for (int ni = 0; ni < 8; ni++) {
                int col = ni*8 + c0;
                float b0 = bias_s[wn*64 + col], b1 = bias_s[wn*64 + col + 1];
                float v0 = 1.f/(1.f + __expf(-(acc[mi][ni][0] + b0)));
                float v1 = 1.f/(1.f + __expf(-(acc[mi][ni][1] + b1)));
                float v2 = 1.f/(1.f + __expf(-(acc[mi][ni][2] + b0)));
                float v3 = 1.f/(1.f + __expf(-(acc[mi][ni][3] + b1)));
                int row = r0 + mi*16;
                *(float2*)(op + (size_t)row*64 + col)     = make_float2(v0, v1);
                *(float2*)(op + (size_t)(row+8)*64 + col) = make_float2(v2, v3);
            }
        }
    } else {
        __nv_bfloat16* Hi = wsel == 0 ? g_Qhi : wsel == 1 ? g_Khi : g_Vhi;
        __nv_bfloat16* Lo = wsel == 0 ? g_Qlo : wsel == 1 ? g_Klo : g_Vlo;
        #pragma unroll
        for (int mi = 0; mi < 2; mi++) {
            #pragma unroll
            for (int ni = 0; ni < 8; ni++) {
                int col = ni*8 + c0;
                float b0 = bias_s[wn*64 + col], b1 = bias_s[wn*64 + col + 1];
                float v0 = acc[mi][ni][0] + b0, v1 = acc[mi][ni][1] + b1;
                float v2 = acc[mi][ni][2] + b0, v3 = acc[mi][ni][3] + b1;
                int row = r0 + mi*16;
                *(uint32_t*)(Hi + base + (size_t)row*64 + col)     = packbf2(v0, v1);
                *(uint32_t*)(Hi + base + (size_t)(row+8)*64 + col) = packbf2(v2, v3);
                float l0 = v0 - bflof(v0), l1 = v1 - bflof(v1);
                float l2 = v2 - bflof(v2), l3 = v3 - bflof(v3);
                *(uint32_t*)(Lo + base + (size_t)row*64 + col)     = packbf2(l0, l1);
                *(uint32_t*)(Lo + base + (size_t)(row+8)*64 + col) = packbf2(l2, l3);
            }
        }
    }
}

// ================= sigma via mma (N=256, fused epilogue) =================
__global__ __launch_bounds__(512) void sigma_mma_kernel(
    const float* __restrict__ bu1, const float* __restrict__ Wu2,
    const float* __restrict__ bu2, float* __restrict__ sigma_out)
{
    __shared__ float bu1_s[256], wu2_s[256];
    __shared__ float red[128][4];
    int t = threadIdx.x, lane = t & 31, wid = t >> 5;
    int wm = wid & 3, wn = wid >> 2;
    int mb = blockIdx.x * 128;

    if (t < 256) { bu1_s[t] = bu1[t]; wu2_s[t] = Wu2[t]; }
    __syncthreads();

    float acc[2][8][4];
    #pragma unroll
    for (int mi = 0; mi < 2; mi++)
        #pragma unroll
        for (int ni = 0; ni < 8; ni++)
            #pragma unroll
            for (int j = 0; j < 4; j++) acc[mi][ni][j] = 0.f;

    mma_gemm_main(g_Xhi, g_Xlo, g_U1hi, g_U1lo, mb, 0, acc);

    int c0 = (lane & 3) * 2;
    float p[2][2] = {{0.f,0.f},{0.f,0.f}};
    #pragma unroll
    for (int mi = 0; mi < 2; mi++) {
        #pragma unroll
        for (int ni = 0; ni < 8; ni++) {
            int col = wn*64 + ni*8 + c0;
            float w0 = wu2_s[col], w1 = wu2_s[col+1];
            float a0 = fmaxf(acc[mi][ni][0] + bu1_s[col],   0.f);
            float a1 = fmaxf(acc[mi][ni][1] + bu1_s[col+1], 0.f);
            float a2 = fmaxf(acc[mi][ni][2] + bu1_s[col],   0.f);
            float a3 = fmaxf(acc[mi][ni][3] + bu1_s[col+1], 0.f);
            p[mi][0] += a0*w0 + a1*w1;
            p[mi][1] += a2*w0 + a3*w1;
        }
    }
    #pragma unroll
    for (int mi = 0; mi < 2; mi++)
        #pragma unroll
        for (int j = 0; j < 2; j++) {
            p[mi][j] += __shfl_xor_sync(0xFFFFFFFF, p[mi][j], 1);
            p[mi][j] += __shfl_xor_sync(0xFFFFFFFF, p[mi][j], 2);
        }
    if ((lane & 3) == 0) {
        #pragma unroll
        for (int mi = 0; mi < 2; mi++)
            #pragma unroll
            for (int j = 0; j < 2; j++)
                red[wm*32 + mi*16 + j*8 + (lane >> 2)][wn] = p[mi][j];
    }
    __syncthreads();
    if (t < 128) {
        float zv = red[t][0] + red[t][1] + red[t][2] + red[t][3] + bu2[0];
        float sp = (zv > 20.f) ? zv : log1pf(expf(zv));
        sigma_out[mb + t] = sp + 1e-6f;
    }
}

// =================================================================
// Tensorized attention, register-resident S (per b, h, 32-row m-tile)
// smem map (bytes):
//   Kh/Vh   @0      : 36864   (K chunk 256x72 bf16 / Vt chunk 64x264 bf16 / ctx partials)
//   Kl/Vl   @36864  : 36864
//   Qh      @73728  : 4608
//   Ql      @78336  : 4608
//   invn    @82944  : 4096
//   rowfac  @87040  : 128
// =================================================================
#define KSTR  72
#define VSTR  264
#define CSTR  68
#define A3_KH  0
#define A3_KL  36864
#define A3_QH  73728
#define A3_QL  78336
#define A3_INV 82944
#define A3_RF  87040
#define ATTN3_SMEM 87168

__global__ __launch_bounds__(256) void attn3_kernel(
    const float* __restrict__ sigma, float* __restrict__ attn_out)
{
    char* smb = s_dyn;
    __nv_bfloat16* Kh = (__nv_bfloat16*)(smb + A3_KH);
    __nv_bfloat16* Kl = (__nv_bfloat16*)(smb + A3_KL);
    __nv_bfloat16* Qh = (__nv_bfloat16*)(smb + A3_QH);
    __nv_bfloat16* Ql = (__nv_bfloat16*)(smb + A3_QL);
    float* invn   = (float*)(smb + A3_INV);
    float* rowfac = (float*)(smb + A3_RF);
    __shared__ float wmax[32][4];
    __shared__ float wsum[32][4];

    int t = threadIdx.x, lane = t & 31, wid = t >> 5;
    int m0 = blockIdx.x * 32;
    int bh = blockIdx.z * NHq + blockIdx.y;
    const __nv_bfloat16* Qhg = g_Qhi + (size_t)bh*Mq*HDq;
    const __nv_bfloat16* Qlg = g_Qlo + (size_t)bh*Mq*HDq;
    const __nv_bfloat16* Khg = g_Khi + (size_t)bh*Mq*HDq;
    const __nv_bfloat16* Klg = g_Klo + (size_t)bh*Mq*HDq;
    const __nv_bfloat16* Vth = g_Vthi + (size_t)bh*HDq*Mq;
    const __nv_bfloat16* Vtl = g_Vtlo + (size_t)bh*HDq*Mq;
    const float* Gg = g_G + (size_t)bh*Mq*HDq;
    float*       Cg = g_ctx + (size_t)bh*Mq*HDq;
    const float* sigb = sigma + blockIdx.z*Mq;

    for (int i = t; i < 1024; i += 256) invn[i] = 1.0f / sigb[i];
    if (t < 32) rowfac[t] = 0.125f / sigb[m0 + t];

    // stage Q tile (32x64 hi/lo)
    {
        int r = t >> 3, seg = t & 7;
        *(uint4*)(Qh + r*KSTR + seg*8) = *(const uint4*)(Qhg + (size_t)(m0 + r)*64 + seg*8);
        *(uint4*)(Ql + r*KSTR + seg*8) = *(const uint4*)(Qlg + (size_t)(m0 + r)*64 + seg*8);
    }

    const int mh = wid >> 2;         // 0..1 (m half)
    const int nw = wid & 3;          // 0..3 (n slice)
    const uint32_t qh_base = smem_u32(Qh) + (uint32_t)((mh*16 + (lane & 15))*KSTR + ((lane >> 4) << 3)) * 2;
    const uint32_t ql_base = smem_u32(Ql) + (uint32_t)((mh*16 + (lane & 15))*KSTR + ((lane >> 4) << 3)) * 2;
    // B-operand lane pattern (validated proj convention)
    const uint32_t koff_lane = (uint32_t)(((lane & 7) + ((lane >> 4) << 3))*KSTR
                              + (((lane >> 3) & 1) << 3)) * 2;
    const int r0 = mh*16 + (lane >> 2);          // local row (0..31)
    const int c0 = (lane & 3) * 2;

    // ---- S = scaled Q Kt, accumulators stay in registers ----
    float accS[4][8][4];
    #pragma unroll
    for (int nc = 0; nc < 4; nc++) {
        __syncthreads();   // Kh/Kl free (1st iter also covers Q/invn staging)
        #pragma unroll
        for (int p = 0; p < 8; p++) {
            int i = p*256 + t;
            int r = i >> 3, seg = i & 7;
            *(uint4*)(Kh + r*KSTR + seg*8) = *(const uint4*)(Khg + (size_t)(nc*256 + r)*64 + seg*8);
            *(uint4*)(Kl + r*KSTR + seg*8) = *(const uint4*)(Klg + (size_t)(nc*256 + r)*64 + seg*8);
        }
        __syncthreads();
        #pragma unroll
        for (int ni = 0; ni < 8; ni++)
            #pragma unroll
            for (int j = 0; j < 4; j++) accS[nc][ni][j] = 0.f;

        #pragma unroll
        for (int ks = 0; ks < 4; ks++) {
            uint32_t ah[4], al[4];
            ldsm4(ah, qh_base + ks*32);
            ldsm4(al, ql_base + ks*32);
            uint32_t bh4[4][4], bl4[4][4];
            #pragma unroll
            for (int g = 0; g < 4; g++) {
                uint32_t kb = koff_lane + (uint32_t)((nw*64 + g*16)*KSTR)*2 + ks*32;
                ldsm4(bh4[g], smem_u32(Kh) + kb);
                ldsm4(bl4[g], smem_u32(Kl) + kb);
            }
            #pragma unroll
            for (int ni = 0; ni < 8; ni++) mma16816(accS[nc][ni], ah, &bh4[ni >> 1][(ni & 1)*2]);
            #pragma unroll
            for (int ni = 0; ni < 8; ni++) mma16816(accS[nc][ni], ah, &bl4[ni >> 1][(ni & 1)*2]);
            #pragma unroll
            for (int ni = 0; ni < 8; ni++) mma16816(accS[nc][ni], al, &bh4[ni >> 1][(ni & 1)*2]);
        }
    }

    // ---- scale by rowfac * invn (in registers) ----
    const float f0 = rowfac[r0], f1 = rowfac[r0 + 8];
    #pragma unroll
    for (int nc = 0; nc < 4; nc++)
        #pragma unroll
        for (int ni = 0; ni < 8; ni++) {
            int col = nc*256 + nw*64 + ni*8 + c0;
            float iv0 = invn[col], iv1 = invn[col + 1];
            accS[nc][ni][0] *= f0*iv0; accS[nc][ni][1] *= f0*iv1;
            accS[nc][ni][2] *= f1*iv0; accS[nc][ni][3] *= f1*iv1;
        }

    // ---- softmax: rowmax (in-thread -> quad shfl -> cross-warp smem) ----
    float mx0 = -1e30f, mx1 = -1e30f;
    #pragma unroll
    for (int nc = 0; nc < 4; nc++)
        #pragma unroll
        for (int ni = 0; ni < 8; ni++) {
            mx0 = fmaxf(mx0, fmaxf(accS[nc][ni][0], accS[nc][ni][1]));
            mx1 = fmaxf(mx1, fmaxf(accS[nc][ni][2], accS[nc][ni][3]));
        }
    mx0 = fmaxf(mx0, __shfl_xor_sync(0xFFFFFFFF, mx0, 1));
    mx0 = fmaxf(mx0, __shfl_xor_sync(0xFFFFFFFF, mx0, 2));
    mx1 = fmaxf(mx1, __shfl_xor_sync(0xFFFFFFFF, mx1, 1));
    mx1 = fmaxf(mx1, __shfl_xor_sync(0xFFFFFFFF, mx1, 2));
    if ((lane & 3) == 0) { wmax[r0][nw] = mx0; wmax[r0 + 8][nw] = mx1; }
    __syncthreads();
    float rm0 = fmaxf(fmaxf(wmax[r0][0], wmax[r0][1]), fmaxf(wmax[r0][2], wmax[r0][3]));
    float rm1 = fmaxf(fmaxf(wmax[r0+8][0], wmax[r0+8][1]), fmaxf(wmax[r0+8][2], wmax[r0+8][3]));

    // ---- exp + rowsum ----
    float s0 = 0.f, s1 = 0.f;
    #pragma unroll
    for (int nc = 0; nc < 4; nc++)
        #pragma unroll
        for (int ni = 0; ni < 8; ni++) {
            float e0 = __expf(accS[nc][ni][0] - rm0);
            float e1 = __expf(accS[nc][ni][1] - rm0);
            float e2 = __expf(accS[nc][ni][2] - rm1);
            float e3 = __expf(accS[nc][ni][3] - rm1);
            accS[nc][ni][0] = e0; accS[nc][ni][1] = e1;
            accS[nc][ni][2] = e2; accS[nc][ni][3] = e3;
            s0 += e0 + e1; s1 += e2 + e3;
        }
    s0 += __shfl_xor_sync(0xFFFFFFFF, s0, 1);
    s0 += __shfl_xor_sync(0xFFFFFFFF, s0, 2);
    s1 += __shfl_xor_sync(0xFFFFFFFF, s1, 1);
    s1 += __shfl_xor_sync(0xFFFFFFFF, s1, 2);
    if ((lane & 3) == 0) { wsum[r0][nw] = s0; wsum[r0 + 8][nw] = s1; }
    __syncthreads();
    float rinv0 = 1.0f / (wsum[r0][0] + wsum[r0][1] + wsum[r0][2] + wsum[r0][3]);
    float rinv1 = 1.0f / (wsum[r0+8][0] + wsum[r0+8][1] + wsum[r0+8][2] + wsum[r0+8][3]);

    // ---- normalize in regs + write attn directly from registers ----
    {
        float* aout = attn_out + ((size_t)bh*Mq + m0) * 1024;
        float* row0 = aout + (size_t)r0*1024;
        float* row1 = aout + (size_t)(r0 + 8)*1024;
        #pragma unroll
        for (int nc = 0; nc < 4; nc++)
            #pragma unroll
            for (int ni = 0; ni < 8; ni++) {
                int col = nc*256 + nw*64 + ni*8 + c0;
                float v0 = accS[nc][ni][0]*rinv0, v1 = accS[nc][ni][1]*rinv0;
                float v2 = accS[nc][ni][2]*rinv1, v3 = accS[nc][ni][3]*rinv1;
                accS[nc][ni][0] = v0; accS[nc][ni][1] = v1;
                accS[nc][ni][2] = v2; accS[nc][ni][3] = v3;
                *(float2*)(row0 + col) = make_float2(v0, v1);
                *(float2*)(row1 + col) = make_float2(v2, v3);
            }
    }

    // ---- ctx = P @ Vt via mma; A-frags packed straight from accS ----
    float ctx[8][4];
    #pragma unroll
    for (int di = 0; di < 8; di++)
        #pragma unroll
        for (int j = 0; j < 4; j++) ctx[di][j] = 0.f;

    const uint32_t vrow_lane = (uint32_t)((lane & 7) + ((lane >> 4) << 3));
    const uint32_t vh_base = smem_u32(Kh);
    const uint32_t vl_base = smem_u32(Kl);

    #pragma unroll
    for (int nc = 0; nc < 4; nc++) {
        __syncthreads();   // Kh/Kl reuse as V staging
        {
            int d = t >> 2, cb = (t & 3) * 64;
            #pragma unroll
            for (int j = 0; j < 8; j++) {
                *(uint4*)(Kh + d*VSTR + cb + j*8) =
                    *(const uint4*)(Vth + (size_t)d*1024 + nc*256 + cb + j*8);
                *(uint4*)(Kl + d*VSTR + cb + j*8) =
                    *(const uint4*)(Vtl + (size_t)d*1024 + nc*256 + cb + j*8);
            }
        }
        __syncthreads();
        #pragma unroll
        for (int ks = 0; ks < 4; ks++) {
            // A fragment (rows r0/r0+8, k-cols = this warp's 16 P columns)
            float p00 = accS[nc][2*ks][0],   p01 = accS[nc][2*ks][1];
            float p02 = accS[nc][2*ks][2],   p03 = accS[nc][2*ks][3];
            float p10 = accS[nc][2*ks+1][0], p11 = accS[nc][2*ks+1][1];
            float p12 = accS[nc][2*ks+1][2], p13 = accS[nc][2*ks+1][3];
            uint32_t ah[4], al[4];
            ah[0] = packbf2(p00, p01); ah[1] = packbf2(p02, p03);
            ah[2] = packbf2(p10, p11); ah[3] = packbf2(p12, p13);
            al[0] = packbf2(p00 - bflof(p00), p01 - bflof(p01));
            al[1] = packbf2(p02 - bflof(p02), p03 - bflof(p03));
            al[2] = packbf2(p10 - bflof(p10), p11 - bflof(p11));
            al[3] = packbf2(p12 - bflof(p12), p13 - bflof(p13));

            uint32_t bcolb = (uint32_t)(nw*64 + ks*16 + (((lane >> 3) & 1) << 3)) * 2;
            uint32_t bvh[4][4], bvl[4][4];
            #pragma unroll
            for (int g = 0; g < 4; g++) {
                uint32_t boffb = (uint32_t)((g*16 + vrow_lane)*VSTR)*2 + bcolb;
                ldsm4(bvh[g], vh_base + boffb);
                ldsm4(bvl[g], vl_base + boffb);
            }
            #pragma unroll
            for (int di = 0; di < 8; di++) mma16816(ctx[di], ah, &bvh[di >> 1][(di & 1)*2]);
            #pragma unroll
            for (int di = 0; di < 8; di++) mma16816(ctx[di], ah, &bvl[di >> 1][(di & 1)*2]);
            #pragma unroll
            for (int di = 0; di < 8; di++) mma16816(ctx[di], al, &bvh[di >> 1][(di & 1)*2]);
        }
    }
    __syncthreads();

    // ---- reduce k-split partials, gate, store ----
    float* part = (float*)Kh;   // [4][32][CSTR]
    #pragma unroll
    for (int di = 0; di < 8; di++) {
        int c = di*8 + c0;
        *(float2*)&part[(nw*32 + r0)*CSTR + c]     = make_float2(ctx[di][0], ctx[di][1]);
        *(float2*)&part[(nw*32 + r0 + 8)*CSTR + c] = make_float2(ctx[di][2], ctx[di][3]);
    }
    __syncthreads();
    {
        int r = t >> 3, d0 = (t & 7) * 8;
        float v[8];
        #pragma unroll
        for (int j = 0; j < 8; j++)
            v[j] = part[r*CSTR + d0 + j] + part[(32 + r)*CSTR + d0 + j]
                 + part[(64 + r)*CSTR + d0 + j] + part[(96 + r)*CSTR + d0 + j];
        float4 g0 = *(const float4*)(Gg + (size_t)(m0 + r)*64 + d0);
        float4 g1 = *(const float4*)(Gg + (size_t)(m0 + r)*64 + d0 + 4);
        float4 o0 = make_float4(v[0]*g0.x, v[1]*g0.y, v[2]*g0.z, v[3]*g0.w);
        float4 o1 = make_float4(v[4]*g1.x, v[5]*g1.y, v[6]*g1.z, v[7]*g1.w);
        *(float4*)(Cg + (size_t)(m0 + r)*64 + d0)     = o0;
        *(float4*)(Cg + (size_t)(m0 + r)*64 + d0 + 4) = o1;
    }
}

// ============ mean over m: 1 block per (b,h) ============
__global__ __launch_bounds__(256) void mean_kernel()
{
    __shared__ float red[256];
    int bh = blockIdx.x;
    int t = threadIdx.x;
    int d = t & 63, grp = t >> 6;
    const float* p = g_ctx + (size_t)bh*Mq*HDq + grp*64 + d;
    float s = 0.f;
    #pragma unroll 8
    for (int m = 0; m < 256; m++) s += p[(size_t)m*256];
    red[t] = s;
    __syncthreads();
    if (t < 64)
        g_fbar[(size_t)bh*64 + d] =
            (red[t] + red[t+64] + red[t+128] + red[t+192]) * (1.0f/1024.0f);
}

// ============ z = fbar @ Wo + bo ============
__global__ __launch_bounds__(256) void z_kernel(
    const float* __restrict__ Wo, const float* __restrict__ bo_,
    float* __restrict__ z)
{
    int n = blockIdx.x * 256 + threadIdx.x;
    int b = blockIdx.y;
    const float* f = g_fbar + b*1024;
    float acc = bo_[n];
    #pragma unroll 4
    for (int k = 0; k < 1024; k++) acc = fmaf(f[k], Wo[(size_t)k*1024 + n], acc);
    z[(size_t)b*1024 + n] = acc;
}

// =================================================================
extern "C" void kernel_launch(void* const* d_in, const int* in_sizes, int n_in,
                              void* d_out, int out_size)
{
    const float* x   = (const float*)d_in[0];
    const float* Wq  = (const float*)d_in[1];
    const float* bq  = (const float*)d_in[2];
    const float* Wk  = (const float*)d_in[3];
    const float* bk  = (const float*)d_in[4];
    const float* Wv  = (const float*)d_in[5];
    const float* bv  = (const float*)d_in[6];
    const float* Wg  = (const float*)d_in[7];
    const float* bg  = (const float*)d_in[8];
    const float* Wo  = (const float*)d_in[9];
    const float* bo  = (const float*)d_in[10];
    const float* Wu1 = (const float*)d_in[11];
    const float* bu1 = (const float*)d_in[12];
    const float* Wu2 = (const float*)d_in[13];
    const float* bu2 = (const float*)d_in[14];

    float* out       = (float*)d_out;
    float* z_out     = out;
    float* attn_out  = out + 8192;
    float* sigma_out = out + 8192 + (size_t)Bq*NHq*Mq*Mq;

    cudaFuncSetAttribute(attn3_kernel,
        cudaFuncAttributeMaxDynamicSharedMemorySize, ATTN3_SMEM);
    cudaFuncSetAttribute(proj_mma_kernel,
        cudaFuncAttributeMaxDynamicSharedMemorySize, GEMM_SMEM);
    cudaFuncSetAttribute(sigma_mma_kernel,
        cudaFuncAttributeMaxDynamicSharedMemorySize, GEMM_SMEM);

    splitx_kernel<<<8192, 256>>>(x);
    tsplitw_kernel<<<dim3(32, 32, 5), 256>>>(Wq, Wk, Wv, Wg, Wu1);
    sigma_mma_kernel<<<64, 512, GEMM_SMEM>>>(bu1, Wu2, bu2, sigma_out);
    proj_mma_kernel<<<dim3(4, 64, 4), 512, GEMM_SMEM>>>(bq, bk, bv, bg);
    transv_kernel<<<dim3(16, 128), 256>>>();
    attn3_kernel<<<dim3(32, 16, 8), 256, ATTN3_SMEM>>>(sigma_out, attn_out);
    mean_kernel<<<128, 256>>>();
    z_kernel<<<dim3(4, 8), 256>>>(Wo, bo, z_out);
}

// round 14
// speedup vs baseline: 2.6583x; 1.1180x over previous
#include <cuda_runtime.h>
#include <cuda_bf16.h>
#include <math.h>
#include <stdint.h>

#define Bq  8
#define Mq  1024
#define Hq  1024
#define NHq 16
#define HDq 64

// -------- scratch (device globals: no allocations allowed) --------
__device__ float g_G[Bq*NHq*Mq*HDq];
__device__ float g_ctx[Bq*NHq*Mq*HDq];
__device__ float g_fbar[Bq*Hq];

__device__ __nv_bfloat16 g_Qhi[Bq*NHq*Mq*HDq];
__device__ __nv_bfloat16 g_Qlo[Bq*NHq*Mq*HDq];
__device__ __nv_bfloat16 g_Khi[Bq*NHq*Mq*HDq];
__device__ __nv_bfloat16 g_Klo[Bq*NHq*Mq*HDq];
__device__ __nv_bfloat16 g_Vhi[Bq*NHq*Mq*HDq];
__device__ __nv_bfloat16 g_Vlo[Bq*NHq*Mq*HDq];
__device__ __nv_bfloat16 g_Vthi[Bq*NHq*HDq*Mq];   // [bh][d][n]
__device__ __nv_bfloat16 g_Vtlo[Bq*NHq*HDq*Mq];

// bf16 hi/lo split GEMM operands
__device__ __nv_bfloat16 g_Xhi[Bq*Mq*Hq];
__device__ __nv_bfloat16 g_Xlo[Bq*Mq*Hq];
__device__ __nv_bfloat16 g_Whi[4*Hq*Hq];      // transposed [n][k]
__device__ __nv_bfloat16 g_Wlo[4*Hq*Hq];
__device__ __nv_bfloat16 g_U1hi[256*Hq];      // transposed [n][k]
__device__ __nv_bfloat16 g_U1lo[256*Hq];

extern __shared__ char s_dyn[];

// ================= helpers =================
__device__ __forceinline__ uint32_t smem_u32(const void* p) {
    uint32_t a;
    asm("{ .reg .u64 t; cvta.to.shared.u64 t, %1; cvt.u32.u64 %0, t; }"
        : "=r"(a) : "l"(p));
    return a;
}
__device__ __forceinline__ void ldsm4(uint32_t* r, uint32_t addr) {
    asm volatile("ldmatrix.sync.aligned.m8n8.x4.shared.b16 {%0,%1,%2,%3}, [%4];"
        : "=r"(r[0]), "=r"(r[1]), "=r"(r[2]), "=r"(r[3]) : "r"(addr));
}
__device__ __forceinline__ void mma16816(float* d, const uint32_t* a, const uint32_t* b) {
    asm volatile("mma.sync.aligned.m16n8k16.row.col.f32.bf16.bf16.f32 "
        "{%0,%1,%2,%3}, {%4,%5,%6,%7}, {%8,%9}, {%0,%1,%2,%3};"
        : "+f"(d[0]), "+f"(d[1]), "+f"(d[2]), "+f"(d[3])
        : "r"(a[0]), "r"(a[1]), "r"(a[2]), "r"(a[3]), "r"(b[0]), "r"(b[1]));
}
__device__ __forceinline__ uint32_t packbf2(float e0, float e1) {
    uint32_t r;
    asm("cvt.rn.bf16x2.f32 %0, %1, %2;" : "=r"(r) : "f"(e1), "f"(e0));
    return r;
}
__device__ __forceinline__ float bflof(float v) {
    return __bfloat162float(__float2bfloat16(v));
}
__device__ __forceinline__ void cpasync16(uint32_t saddr, const void* g) {
    asm volatile("cp.async.cg.shared.global [%0], [%1], 16;"
                 :: "r"(saddr), "l"(g) : "memory");
}
#define CP_COMMIT() asm volatile("cp.async.commit_group;" ::: "memory")
#define CP_WAIT(n)  asm volatile("cp.async.wait_group %0;" :: "n"(n) : "memory")

// ================= prep: split X into bf16 hi/lo =================
__global__ __launch_bounds__(256) void splitx_kernel(const float* __restrict__ x)
{
    size_t i = ((size_t)blockIdx.x * 256 + threadIdx.x) * 4;
    float4 v = *(const float4*)(x + i);
    __nv_bfloat16 h0 = __float2bfloat16(v.x);
    __nv_bfloat16 h1 = __float2bfloat16(v.y);
    __nv_bfloat16 h2 = __float2bfloat16(v.z);
    __nv_bfloat16 h3 = __float2bfloat16(v.w);
    __nv_bfloat16 l0 = __float2bfloat16(v.x - __bfloat162float(h0));
    __nv_bfloat16 l1 = __float2bfloat16(v.y - __bfloat162float(h1));
    __nv_bfloat16 l2 = __float2bfloat16(v.z - __bfloat162float(h2));
    __nv_bfloat16 l3 = __float2bfloat16(v.w - __bfloat162float(h3));
    *(__nv_bfloat162*)(g_Xhi + i)     = __nv_bfloat162(h0, h1);
    *(__nv_bfloat162*)(g_Xhi + i + 2) = __nv_bfloat162(h2, h3);
    *(__nv_bfloat162*)(g_Xlo + i)     = __nv_bfloat162(l0, l1);
    *(__nv_bfloat162*)(g_Xlo + i + 2) = __nv_bfloat162(l2, l3);
}

// ============ prep: transpose + split W's ([K,N] -> [N,K] bf16 hi/lo) ============
__global__ __launch_bounds__(256) void tsplitw_kernel(
    const float* __restrict__ Wq, const float* __restrict__ Wk,
    const float* __restrict__ Wv, const float* __restrict__ Wg,
    const float* __restrict__ Wu1)
{
    __shared__ float tile[32][33];
    int z = blockIdx.z;
    const float* W; __nv_bfloat16 *oh, *ol; int N;
    if (z < 4) {
        W = (z == 0 ? Wq : z == 1 ? Wk : z == 2 ? Wv : Wg); N = 1024;
        oh = g_Whi + (size_t)z * 1024 * 1024; ol = g_Wlo + (size_t)z * 1024 * 1024;
    } else {
        W = Wu1; N = 256; oh = g_U1hi; ol = g_U1lo;
    }
    int kb = blockIdx.x * 32, nb = blockIdx.y * 32;
    if (nb >= N) return;
    int t = threadIdx.x, tx = t & 31, ty = t >> 5;
    #pragma unroll
    for (int i = 0; i < 4; i++)
        tile[ty + 8*i][tx] = W[(size_t)(kb + ty + 8*i) * N + nb + tx];
    __syncthreads();
    #pragma unroll
    for (int i = 0; i < 4; i++) {
        float v = tile[tx][ty + 8*i];
        __nv_bfloat16 h = __float2bfloat16(v);
        __nv_bfloat16 l = __float2bfloat16(v - __bfloat162float(h));
        size_t oidx = (size_t)(nb + ty + 8*i) * 1024 + kb + tx;
        oh[oidx] = h; ol[oidx] = l;
    }
}

// ============ prep: transpose V hi/lo to [bh][d][n] ============
__global__ __launch_bounds__(256) void transv_kernel()
{
    __shared__ __nv_bfloat16 th[64][72];
    __shared__ __nv_bfloat16 tl[64][72];
    int bh = blockIdx.y;
    int nb = blockIdx.x * 64;
    const __nv_bfloat16* sh = g_Vhi + ((size_t)bh*1024 + nb)*64;
    const __nv_bfloat16* sl = g_Vlo + ((size_t)bh*1024 + nb)*64;
    int t = threadIdx.x;
    int r = t >> 2, cseg = (t & 3)*16;
    *(uint4*)&th[r][cseg]     = *(const uint4*)(sh + (size_t)r*64 + cseg);
    *(uint4*)&th[r][cseg + 8] = *(const uint4*)(sh + (size_t)r*64 + cseg + 8);
    *(uint4*)&tl[r][cseg]     = *(const uint4*)(sl + (size_t)r*64 + cseg);
    *(uint4*)&tl[r][cseg + 8] = *(const uint4*)(sl + (size_t)r*64 + cseg + 8);
    __syncthreads();
    int d = t >> 2, nseg = (t & 3)*16;
    __nv_bfloat16 vh[16], vl[16];
    #pragma unroll
    for (int j = 0; j < 16; j++) { vh[j] = th[nseg + j][d]; vl[j] = tl[nseg + j][d]; }
    __nv_bfloat16* oh = g_Vthi + (size_t)bh*65536 + (size_t)d*1024 + nb + nseg;
    __nv_bfloat16* ol = g_Vtlo + (size_t)bh*65536 + (size_t)d*1024 + nb + nseg;
    *(uint4*)(oh)     = *(uint4*)&vh[0];
    *(uint4*)(oh + 8) = *(uint4*)&vh[8];
    *(uint4*)(ol)     = *(uint4*)&vl[0];
    *(uint4*)(ol + 8) = *(uint4*)&vl[8];
}

// ================= mma.sync GEMM core (proj/sigma) =================
#define ASTR 40
#define BSTR 40
#define A_ELE (128*ASTR)
#define B_ELE (256*BSTR)
#define BUF_ELE (2*A_ELE + 2*B_ELE)
#define GEMM_SMEM (2*BUF_ELE*2)

__device__ __forceinline__ void mma_gemm_main(
    const __nv_bfloat16* __restrict__ Ah, const __nv_bfloat16* __restrict__ Al,
    const __nv_bfloat16* __restrict__ Bh, const __nv_bfloat16* __restrict__ Bl,
    int mb, int nb, float acc[2][8][4])
{
    __nv_bfloat16* sm = (__nv_bfloat16*)s_dyn;
    const uint32_t smb = smem_u32(sm);
    const int t = threadIdx.x, lane = t & 31, wid = t >> 5;
    const int wm = wid & 3, wn = wid >> 2;

    const int aoff = (wm*32 + (lane & 15))*ASTR + ((lane >> 4) << 3);
    const int boff = (wn*64 + (lane & 7) + ((lane >> 4) << 3))*BSTR
                   + (((lane >> 3) & 1) << 3);

    const int arow = t >> 2;
    const int aseg = (t & 3) * 8;

    const __nv_bfloat16* pAh = Ah + (size_t)(mb + arow)*1024 + aseg;
    const __nv_bfloat16* pAl = Al + (size_t)(mb + arow)*1024 + aseg;
    const __nv_bfloat16* pB0h = Bh + (size_t)(nb + arow)*1024 + aseg;
    const __nv_bfloat16* pB1h = Bh + (size_t)(nb + arow + 128)*1024 + aseg;
    const __nv_bfloat16* pB0l = Bl + (size_t)(nb + arow)*1024 + aseg;
    const __nv_bfloat16* pB1l = Bl + (size_t)(nb + arow + 128)*1024 + aseg;

    const int stA = arow*ASTR + aseg;
    const int stB0 = arow*BSTR + aseg;
    const int stB1 = (arow + 128)*BSTR + aseg;

    uint4 ra_h, ra_l, rb0h, rb1h, rb0l, rb1l;
    ra_h = *(const uint4*)(pAh);  ra_l = *(const uint4*)(pAl);
    rb0h = *(const uint4*)(pB0h); rb1h = *(const uint4*)(pB1h);
    rb0l = *(const uint4*)(pB0l); rb1l = *(const uint4*)(pB1l);

    for (int c = 0; c < 32; c++) {
        const int bo = (c & 1) * BUF_ELE;
        *(uint4*)(sm + bo + stA)                    = ra_h;
        *(uint4*)(sm + bo + A_ELE + stA)            = ra_l;
        *(uint4*)(sm + bo + 2*A_ELE + stB0)         = rb0h;
        *(uint4*)(sm + bo + 2*A_ELE + stB1)         = rb1h;
        *(uint4*)(sm + bo + 2*A_ELE + B_ELE + stB0) = rb0l;
        *(uint4*)(sm + bo + 2*A_ELE + B_ELE + stB1) = rb1l;
        __syncthreads();
        if (c < 31) {
            int kb = (c + 1) * 32;
            ra_h = *(const uint4*)(pAh + kb);  ra_l = *(const uint4*)(pAl + kb);
            rb0h = *(const uint4*)(pB0h + kb); rb1h = *(const uint4*)(pB1h + kb);
            rb0l = *(const uint4*)(pB0l + kb); rb1l = *(const uint4*)(pB1l + kb);
        }
        #pragma unroll
        for (int ks = 0; ks < 2; ks++) {
            const int koff = ks * 16;
            uint32_t ah[2][4], al2[2][4], bhf[4][4], blf[4][4];
            #pragma unroll
            for (int mi = 0; mi < 2; mi++) {
                uint32_t ad = smb + (uint32_t)(bo + aoff + mi*16*ASTR + koff) * 2;
                ldsm4(ah[mi], ad);
                ldsm4(al2[mi], ad + A_ELE*2);
            }
            #pragma unroll
            for (int n2 = 0; n2 < 4; n2++) {
                uint32_t bd = smb + (uint32_t)(bo + 2*A_ELE + boff + n2*16*BSTR + koff) * 2;
                ldsm4(bhf[n2], bd);
                ldsm4(blf[n2], bd + B_ELE*2);
            }
            #pragma unroll
            for (int mi = 0; mi < 2; mi++)
                #pragma unroll
                for (int ni = 0; ni < 8; ni++)
                    mma16816(acc[mi][ni], ah[mi], &bhf[ni >> 1][(ni & 1) * 2]);
            #pragma unroll
            for (int mi = 0; mi < 2; mi++)
                #pragma unroll
                for (int ni = 0; ni < 8; ni++)
                    mma16816(acc[mi][ni], ah[mi], &blf[ni >> 1][(ni & 1) * 2]);
            #pragma unroll
            for (int mi = 0; mi < 2; mi++)
                #pragma unroll
                for (int ni = 0; ni < 8; ni++)
                    mma16816(acc[mi][ni], al2[mi], &bhf[ni >> 1][(ni & 1) * 2]);
        }
    }
}

// ================= projections via mma =================
// Outputs: Q,K,V -> bf16 hi/lo; G -> fp32 (sigmoid)
__global__ __launch_bounds__(512) void proj_mma_kernel(
    const float* __restrict__ bq_, const float* __restrict__ bk_,
    const float* __restrict__ bv_, const float* __restrict__ bg_)
{
    __shared__ float bias_s[256];
    int t = threadIdx.x, lane = t & 31, wid = t >> 5;
    int wn = wid >> 2, wm = wid & 3;
    int mb = blockIdx.y * 128;
    int nb = blockIdx.x * 256;
    int wsel = blockIdx.z;
    const __nv_bfloat16* Bh = g_Whi + (size_t)wsel * 1024 * 1024;
    const __nv_bfloat16* Bl = g_Wlo + (size_t)wsel * 1024 * 1024;
    const float* bias = wsel == 0 ? bq_ : wsel == 1 ? bk_ : wsel == 2 ? bv_ : bg_;

    if (t < 256) bias_s[t] = bias[nb + t];
    __syncthreads();

    float acc[2][8][4];
    #pragma unroll
    for (int mi = 0; mi < 2; mi++)
        #pragma unroll
        for (int ni = 0; ni < 8; ni++)
            #pragma unroll
            for (int j = 0; j < 4; j++) acc[mi][ni][j] = 0.f;

    mma_gemm_main(g_Xhi, g_Xlo, Bh, Bl, mb, nb, acc);

    int b = mb >> 10, mloc = mb & 1023;
    int hh = (nb >> 6) + wn;
    size_t base = ((size_t)(b*NHq + hh)*Mq + mloc)*HDq;
    int r0 = wm*32 + (lane >> 2);
    int c0 = (lane & 3) * 2;

    if (wsel == 3) {
        float* op = g_G + base;
        #pragma unroll
        for (int mi = 0; mi < 2; mi++) {
            #pragma unroll
            for (int ni = 0; ni < 8; ni++) {
                int col = ni*8 + c0;
                float b0 = bias_s[wn*64 + col], b1 = bias_s[wn*64 + col + 1];
                float v0 = 1.f/(1.f + __expf(-(acc[mi][ni][0] + b0)));
                float v1 = 1.f/(1.f + __expf(-(acc[mi][ni][1] + b1)));
                float v2 = 1.f/(1.f + __expf(-(acc[mi][ni][2] + b0)));
                float v3 = 1.f/(1.f + __expf(-(acc[mi][ni][3] + b1)));
                int row = r0 + mi*16;
                *(float2*)(op + (size_t)row*64 + col)     = make_float2(v0, v1);
                *(float2*)(op + (size_t)(row+8)*64 + col) = make_float2(v2, v3);
            }
        }
    } else {
        __nv_bfloat16* Hi = wsel == 0 ? g_Qhi : wsel == 1 ? g_Khi : g_Vhi;
        __nv_bfloat16* Lo = wsel == 0 ? g_Qlo : wsel == 1 ? g_Klo : g_Vlo;
        #pragma unroll
        for (int mi = 0; mi < 2; mi++) {
            #pragma unroll
            for (int ni = 0; ni < 8; ni++) {
                int col = ni*8 + c0;
                float b0 = bias_s[wn*64 + col], b1 = bias_s[wn*64 + col + 1];
                float v0 = acc[mi][ni][0] + b0, v1 = acc[mi][ni][1] + b1;
                float v2 = acc[mi][ni][2] + b0, v3 = acc[mi][ni][3] + b1;
                int row = r0 + mi*16;
                *(uint32_t*)(Hi + base + (size_t)row*64 + col)     = packbf2(v0, v1);
                *(uint32_t*)(Hi + base + (size_t)(row+8)*64 + col) = packbf2(v2, v3);
                float l0 = v0 - bflof(v0), l1 = v1 - bflof(v1);
                float l2 = v2 - bflof(v2), l3 = v3 - bflof(v3);
                *(uint32_t*)(Lo + base + (size_t)row*64 + col)     = packbf2(l0, l1);
                *(uint32_t*)(Lo + base + (size_t)(row+8)*64 + col) = packbf2(l2, l3);
            }
        }
    }
}

// ================= sigma via mma (N=256, fused epilogue) =================
__global__ __launch_bounds__(512) void sigma_mma_kernel(
    const float* __restrict__ bu1, const float* __restrict__ Wu2,
    const float* __restrict__ bu2, float* __restrict__ sigma_out)
{
    __shared__ float bu1_s[256], wu2_s[256];
    __shared__ float red[128][4];
    int t = threadIdx.x, lane = t & 31, wid = t >> 5;
    int wm = wid & 3, wn = wid >> 2;
    int mb = blockIdx.x * 128;

    if (t < 256) { bu1_s[t] = bu1[t]; wu2_s[t] = Wu2[t]; }
    __syncthreads();

    float acc[2][8][4];
    #pragma unroll
    for (int mi = 0; mi < 2; mi++)
        #pragma unroll
        for (int ni = 0; ni < 8; ni++)
            #pragma unroll
            for (int j = 0; j < 4; j++) acc[mi][ni][j] = 0.f;

    mma_gemm_main(g_Xhi, g_Xlo, g_U1hi, g_U1lo, mb, 0, acc);

    int c0 = (lane & 3) * 2;
    float p[2][2] = {{0.f,0.f},{0.f,0.f}};
    #pragma unroll
    for (int mi = 0; mi < 2; mi++) {
        #pragma unroll
        for (int ni = 0; ni < 8; ni++) {
            int col = wn*64 + ni*8 + c0;
            float w0 = wu2_s[col], w1 = wu2_s[col+1];
            float a0 = fmaxf(acc[mi][ni][0] + bu1_s[col],   0.f);
            float a1 = fmaxf(acc[mi][ni][1] + bu1_s[col+1], 0.f);
            float a2 = fmaxf(acc[mi][ni][2] + bu1_s[col],   0.f);
            float a3 = fmaxf(acc[mi][ni][3] + bu1_s[col+1], 0.f);
            p[mi][0] += a0*w0 + a1*w1;
            p[mi][1] += a2*w0 + a3*w1;
        }
    }
    #pragma unroll
    for (int mi = 0; mi < 2; mi++)
        #pragma unroll
        for (int j = 0; j < 2; j++) {
            p[mi][j] += __shfl_xor_sync(0xFFFFFFFF, p[mi][j], 1);
            p[mi][j] += __shfl_xor_sync(0xFFFFFFFF, p[mi][j], 2);
        }
    if ((lane & 3) == 0) {
        #pragma unroll
        for (int mi = 0; mi < 2; mi++)
            #pragma unroll
            for (int j = 0; j < 2; j++)
                red[wm*32 + mi*16 + j*8 + (lane >> 2)][wn] = p[mi][j];
    }
    __syncthreads();
    if (t < 128) {
        float zv = red[t][0] + red[t][1] + red[t][2] + red[t][3] + bu2[0];
        float sp = (zv > 20.f) ? zv : log1pf(expf(zv));
        sigma_out[mb + t] = sp + 1e-6f;
    }
}

// =================================================================
// Tensorized attention, register-resident S + cp.async double-buffered K/V
// smem map (bytes):
//   KH0 @0      : 36864      KL0 @36864  : 36864
//   KH1 @73728  : 36864      KL1 @110592 : 36864
//   Qh  @147456 : 4608       Ql  @152064 : 4608
//   invn@156672 : 4096       rowfac @160768 : 128
// =================================================================
#define KSTR  72
#define VSTR  264
#define CSTR  68
#define A4_BUF0 0
#define A4_BUF1 73728
#define A4_LOFF 36864
#define A4_QH  147456
#define A4_QL  152064
#define A4_INV 156672
#define A4_RF  160768
#define ATTN4_SMEM 160896

__global__ __launch_bounds__(256) void attn4_kernel(
    const float* __restrict__ sigma, float* __restrict__ attn_out)
{
    char* smb = s_dyn;
    __nv_bfloat16* Qh = (__nv_bfloat16*)(smb + A4_QH);
    __nv_bfloat16* Ql = (__nv_bfloat16*)(smb + A4_QL);
    float* invn   = (float*)(smb + A4_INV);
    float* rowfac = (float*)(smb + A4_RF);
    __shared__ float wmax[32][4];
    __shared__ float wsum[32][4];

    int t = threadIdx.x, lane = t & 31, wid = t >> 5;
    int m0 = blockIdx.x * 32;
    int bh = blockIdx.z * NHq + blockIdx.y;
    const __nv_bfloat16* Qhg = g_Qhi + (size_t)bh*Mq*HDq;
    const __nv_bfloat16* Qlg = g_Qlo + (size_t)bh*Mq*HDq;
    const __nv_bfloat16* Khg = g_Khi + (size_t)bh*Mq*HDq;
    const __nv_bfloat16* Klg = g_Klo + (size_t)bh*Mq*HDq;
    const __nv_bfloat16* Vth = g_Vthi + (size_t)bh*HDq*Mq;
    const __nv_bfloat16* Vtl = g_Vtlo + (size_t)bh*HDq*Mq;
    const float* Gg = g_G + (size_t)bh*Mq*HDq;
    float*       Cg = g_ctx + (size_t)bh*Mq*HDq;
    const float* sigb = sigma + blockIdx.z*Mq;

    const uint32_t sm0 = smem_u32(smb);
    const uint32_t buf_u32[2] = { sm0 + A4_BUF0, sm0 + A4_BUF1 };

    // K-chunk staging coords: row = (t>>3) + p*32 for p<8 -> rows 0..255; seg = t&7
    const int kr   = t >> 3;
    const int kseg = (t & 7) * 8;
    // V-chunk staging coords: d = t>>2 (0..63), cols (t&3)*64 + j*8 (j<8) -> 0..255
    const int vd  = t >> 2;
    const int vcb = (t & 3) * 64;

    for (int i = t; i < 1024; i += 256) invn[i] = 1.0f / sigb[i];
    if (t < 32) rowfac[t] = 0.125f / sigb[m0 + t];

    // stage Q tile (32x64 hi/lo) — regular stores
    {
        int r = t >> 3, seg = t & 7;
        *(uint4*)(Qh + r*KSTR + seg*8) = *(const uint4*)(Qhg + (size_t)(m0 + r)*64 + seg*8);
        *(uint4*)(Ql + r*KSTR + seg*8) = *(const uint4*)(Qlg + (size_t)(m0 + r)*64 + seg*8);
    }

    const int mh = wid >> 2;
    const int nw = wid & 3;
    const uint32_t qh_base = smem_u32(Qh) + (uint32_t)((mh*16 + (lane & 15))*KSTR + ((lane >> 4) << 3)) * 2;
    const uint32_t ql_base = smem_u32(Ql) + (uint32_t)((mh*16 + (lane & 15))*KSTR + ((lane >> 4) << 3)) * 2;
    const uint32_t koff_lane = (uint32_t)(((lane & 7) + ((lane >> 4) << 3))*KSTR
                              + (((lane >> 3) & 1) << 3)) * 2;
    const int r0 = mh*16 + (lane >> 2);
    const int c0 = (lane & 3) * 2;

    // ---- prologue: async-stage K chunk 0 into buf0 (FULL 256 rows) ----
    #pragma unroll
    for (int p = 0; p < 8; p++) {
        int r = kr + p*32;
        uint32_t so = (uint32_t)(r*KSTR + kseg) * 2;
        cpasync16(buf_u32[0] + so,            Khg + (size_t)r*64 + kseg);
        cpasync16(buf_u32[0] + A4_LOFF + so,  Klg + (size_t)r*64 + kseg);
    }
    CP_COMMIT();

    // ---- S = scaled Q Kt, register accumulators, pipelined K ----
    float accS[4][8][4];
    #pragma unroll
    for (int nc = 0; nc < 4; nc++) {
        if (nc < 3) {   // prefetch next K chunk into other buffer
            uint32_t bu = buf_u32[(nc + 1) & 1];
            #pragma unroll
            for (int p = 0; p < 8; p++) {
                int r = kr + p*32;
                uint32_t so = (uint32_t)(r*KSTR + kseg) * 2;
                cpasync16(bu + so,           Khg + (size_t)((nc+1)*256 + r)*64 + kseg);
                cpasync16(bu + A4_LOFF + so, Klg + (size_t)((nc+1)*256 + r)*64 + kseg);
            }
            CP_COMMIT();
            CP_WAIT(1);
        } else {
            CP_WAIT(0);
        }
        __syncthreads();
        const uint32_t kh_b = buf_u32[nc & 1];
        const uint32_t kl_b = kh_b + A4_LOFF;

        #pragma unroll
        for (int ni = 0; ni < 8; ni++)
            #pragma unroll
            for (int j = 0; j < 4; j++) accS[nc][ni][j] = 0.f;

        #pragma unroll
        for (int ks = 0; ks < 4; ks++) {
            uint32_t ah[4], al[4];
            ldsm4(ah, qh_base + ks*32);
            ldsm4(al, ql_base + ks*32);
            uint32_t bh4[4][4], bl4[4][4];
            #pragma unroll
            for (int g = 0; g < 4; g++) {
                uint32_t kb = koff_lane + (uint32_t)((nw*64 + g*16)*KSTR)*2 + ks*32;
                ldsm4(bh4[g], kh_b + kb);
                ldsm4(bl4[g], kl_b + kb);
            }
            #pragma unroll
            for (int ni = 0; ni < 8; ni++) mma16816(accS[nc][ni], ah, &bh4[ni >> 1][(ni & 1)*2]);
            #pragma unroll
            for (int ni = 0; ni < 8; ni++) mma16816(accS[nc][ni], ah, &bl4[ni >> 1][(ni & 1)*2]);
            #pragma unroll
            for (int ni = 0; ni < 8; ni++) mma16816(accS[nc][ni], al, &bh4[ni >> 1][(ni & 1)*2]);
        }
        __syncthreads();   // all warps done with buf[nc&1] before next prefetch overwrites it
    }

    // ---- async-stage V chunk 0 into buf0 (overlaps softmax below) ----
    #pragma unroll
    for (int j = 0; j < 8; j++) {
        uint32_t so = (uint32_t)(vd*VSTR + vcb + j*8) * 2;
        cpasync16(buf_u32[0] + so,           Vth + (size_t)vd*1024 + vcb + j*8);
        cpasync16(buf_u32[0] + A4_LOFF + so, Vtl + (size_t)vd*1024 + vcb + j*8);
    }
    CP_COMMIT();

    // ---- scale by rowfac * invn (in registers) ----
    const float f0 = rowfac[r0], f1 = rowfac[r0 + 8];
    #pragma unroll
    for (int nc = 0; nc < 4; nc++)
        #pragma unroll
        for (int ni = 0; ni < 8; ni++) {
            int col = nc*256 + nw*64 + ni*8 + c0;
            float iv0 = invn[col], iv1 = invn[col + 1];
            accS[nc][ni][0] *= f0*iv0; accS[nc][ni][1] *= f0*iv1;
            accS[nc][ni][2] *= f1*iv0; accS[nc][ni][3] *= f1*iv1;
        }

    // ---- softmax: rowmax ----
    float mx0 = -1e30f, mx1 = -1e30f;
    #pragma unroll
    for (int nc = 0; nc < 4; nc++)
        #pragma unroll
        for (int ni = 0; ni < 8; ni++) {
            mx0 = fmaxf(mx0, fmaxf(accS[nc][ni][0], accS[nc][ni][1]));
            mx1 = fmaxf(mx1, fmaxf(accS[nc][ni][2], accS[nc][ni][3]));
        }
    mx0 = fmaxf(mx0, __shfl_xor_sync(0xFFFFFFFF, mx0, 1));
    mx0 = fmaxf(mx0, __shfl_xor_sync(0xFFFFFFFF, mx0, 2));
    mx1 = fmaxf(mx1, __shfl_xor_sync(0xFFFFFFFF, mx1, 1));
    mx1 = fmaxf(mx1, __shfl_xor_sync(0xFFFFFFFF, mx1, 2));
    if ((lane & 3) == 0) { wmax[r0][nw] = mx0; wmax[r0 + 8][nw] = mx1; }
    __syncthreads();
    float rm0 = fmaxf(fmaxf(wmax[r0][0], wmax[r0][1]), fmaxf(wmax[r0][2], wmax[r0][3]));
    float rm1 = fmaxf(fmaxf(wmax[r0+8][0], wmax[r0+8][1]), fmaxf(wmax[r0+8][2], wmax[r0+8][3]));

    // ---- exp + rowsum ----
    float s0 = 0.f, s1 = 0.f;
    #pragma unroll
    for (int nc = 0; nc < 4; nc++)
        #pragma unroll
        for (int ni = 0; ni < 8; ni++) {
            float e0 = __expf(accS[nc][ni][0] - rm0);
            float e1 = __expf(accS[nc][ni][1] - rm0);
            float e2 = __expf(accS[nc][ni][2] - rm1);
            float e3 = __expf(accS[nc][ni][3] - rm1);
            accS[nc][ni][0] = e0; accS[nc][ni][1] = e1;
            accS[nc][ni][2] = e2; accS[nc][ni][3] = e3;
            s0 += e0 + e1; s1 += e2 + e3;
        }
    s0 += __shfl_xor_sync(0xFFFFFFFF, s0, 1);
    s0 += __shfl_xor_sync(0xFFFFFFFF, s0, 2);
    s1 += __shfl_xor_sync(0xFFFFFFFF, s1, 1);
    s1 += __shfl_xor_sync(0xFFFFFFFF, s1, 2);
    if ((lane & 3) == 0) { wsum[r0][nw] = s0; wsum[r0 + 8][nw] = s1; }
    __syncthreads();
    float rinv0 = 1.0f / (wsum[r0][0] + wsum[r0][1] + wsum[r0][2] + wsum[r0][3]);
    float rinv1 = 1.0f / (wsum[r0+8][0] + wsum[r0+8][1] + wsum[r0+8][2] + wsum[r0+8][3]);

    // ---- normalize in regs + write attn directly from registers ----
    {
        float* aout = attn_out + ((size_t)bh*Mq + m0) * 1024;
        float* row0 = aout + (size_t)r0*1024;
        float* row1 = aout + (size_t)(r0 + 8)*1024;
        #pragma unroll
        for (int nc = 0; nc < 4; nc++)
            #pragma unroll
            for (int ni = 0; ni < 8; ni++) {
                int col = nc*256 + nw*64 + ni*8 + c0;
                float v0 = accS[nc][ni][0]*rinv0, v1 = accS[nc][ni][1]*rinv0;
                float v2 = accS[nc][ni][2]*rinv1, v3 = accS[nc][ni][3]*rinv1;
                accS[nc][ni][0] = v0; accS[nc][ni][1] = v1;
                accS[nc][ni][2] = v2; accS[nc][ni][3] = v3;
                *(float2*)(row0 + col) = make_float2(v0, v1);
                *(float2*)(row1 + col) = make_float2(v2, v3);
            }
    }

    // ---- ctx = P @ Vt via mma; pipelined V ----
    float ctx[8][4];
    #pragma unroll
    for (int di = 0; di < 8; di++)
        #pragma unroll
        for (int j = 0; j < 4; j++) ctx[di][j] = 0.f;

    const uint32_t vrow_lane = (uint32_t)((lane & 7) + ((lane >> 4) << 3));

    #pragma unroll
    for (int nc = 0; nc < 4; nc++) {
        if (nc < 3) {
            uint32_t bu = buf_u32[(nc + 1) & 1];
            #pragma unroll
            for (int j = 0; j < 8; j++) {
                uint32_t so = (uint32_t)(vd*VSTR + vcb + j*8) * 2;
                cpasync16(bu + so,           Vth + (size_t)vd*1024 + (nc+1)*256 + vcb + j*8);
                cpasync16(bu + A4_LOFF + so, Vtl + (size_t)vd*1024 + (nc+1)*256 + vcb + j*8);
            }
            CP_COMMIT();
            CP_WAIT(1);
        } else {
            CP_WAIT(0);
        }
        __syncthreads();
        const uint32_t vh_b = buf_u32[nc & 1];
        const uint32_t vl_b = vh_b + A4_LOFF;

        #pragma unroll
        for (int ks = 0; ks < 4; ks++) {
            float p00 = accS[nc][2*ks][0],   p01 = accS[nc][2*ks][1];
            float p02 = accS[nc][2*ks][2],   p03 = accS[nc][2*ks][3];
            float p10 = accS[nc][2*ks+1][0], p11 = accS[nc][2*ks+1][1];
            float p12 = accS[nc][2*ks+1][2], p13 = accS[nc][2*ks+1][3];
            uint32_t ah[4], al[4];
            ah[0] = packbf2(p00, p01); ah[1] = packbf2(p02, p03);
            ah[2] = packbf2(p10, p11); ah[3] = packbf2(p12, p13);
            al[0] = packbf2(p00 - bflof(p00), p01 - bflof(p01));
            al[1] = packbf2(p02 - bflof(p02), p03 - bflof(p03));
            al[2] = packbf2(p10 - bflof(p10), p11 - bflof(p11));
            al[3] = packbf2(p12 - bflof(p12), p13 - bflof(p13));

            uint32_t bcolb = (uint32_t)(nw*64 + ks*16 + (((lane >> 3) & 1) << 3)) * 2;
            uint32_t bvh[4][4], bvl[4][4];
            #pragma unroll
            for (int g = 0; g < 4; g++) {
                uint32_t boffb = (uint32_t)((g*16 + vrow_lane)*VSTR)*2 + bcolb;
                ldsm4(bvh[g], vh_b + boffb);
                ldsm4(bvl[g], vl_b + boffb);
            }
            #pragma unroll
            for (int di = 0; di < 8; di++) mma16816(ctx[di], ah, &bvh[di >> 1][(di & 1)*2]);
            #pragma unroll
            for (int di = 0; di < 8; di++) mma16816(ctx[di], ah, &bvl[di >> 1][(di & 1)*2]);
            #pragma unroll
            for (int di = 0; di < 8; di++) mma16816(ctx[di], al, &bvh[di >> 1][(di & 1)*2]);
        }
        __syncthreads();
    }

    // ---- reduce k-split partials, gate, store ----
    float* part = (float*)(smb + A4_BUF0);   // [4][32][CSTR]
    #pragma unroll
    for (int di = 0; di < 8; di++) {
        int c = di*8 + c0;
        *(float2*)&part[(nw*32 + r0)*CSTR + c]     = make_float2(ctx[di][0], ctx[di][1]);
        *(float2*)&part[(nw*32 + r0 + 8)*CSTR + c] = make_float2(ctx[di][2], ctx[di][3]);
    }
    __syncthreads();
    {
        int r = t >> 3, d0 = (t & 7) * 8;
        float v[8];
        #pragma unroll
        for (int j = 0; j < 8; j++)
            v[j] = part[r*CSTR + d0 + j] + part[(32 + r)*CSTR + d0 + j]
                 + part[(64 + r)*CSTR + d0 + j] + part[(96 + r)*CSTR + d0 + j];
        float4 g0 = *(const float4*)(Gg + (size_t)(m0 + r)*64 + d0);
        float4 g1 = *(const float4*)(Gg + (size_t)(m0 + r)*64 + d0 + 4);
        float4 o0 = make_float4(v[0]*g0.x, v[1]*g0.y, v[2]*g0.z, v[3]*g0.w);
        float4 o1 = make_float4(v[4]*g1.x, v[5]*g1.y, v[6]*g1.z, v[7]*g1.w);
        *(float4*)(Cg + (size_t)(m0 + r)*64 + d0)     = o0;
        *(float4*)(Cg + (size_t)(m0 + r)*64 + d0 + 4) = o1;
    }
}

// ============ mean over m: 1 block per (b,h) ============
__global__ __launch_bounds__(256) void mean_kernel()
{
    __shared__ float red[256];
    int bh = blockIdx.x;
    int t = threadIdx.x;
    int d = t & 63, grp = t >> 6;
    const float* p = g_ctx + (size_t)bh*Mq*HDq + grp*64 + d;
    float s = 0.f;
    #pragma unroll 8
    for (int m = 0; m < 256; m++) s += p[(size_t)m*256];
    red[t] = s;
    __syncthreads();
    if (t < 64)
        g_fbar[(size_t)bh*64 + d] =
            (red[t] + red[t+64] + red[t+128] + red[t+192]) * (1.0f/1024.0f);
}

// ============ z = fbar @ Wo + bo ============
__global__ __launch_bounds__(256) void z_kernel(
    const float* __restrict__ Wo, const float* __restrict__ bo_,
    float* __restrict__ z)
{
    int n = blockIdx.x * 256 + threadIdx.x;
    int b = blockIdx.y;
    const float* f = g_fbar + b*1024;
    float acc = bo_[n];
    #pragma unroll 4
    for (int k = 0; k < 1024; k++) acc = fmaf(f[k], Wo[(size_t)k*1024 + n], acc);
    z[(size_t)b*1024 + n] = acc;
}

// =================================================================
extern "C" void kernel_launch(void* const* d_in, const int* in_sizes, int n_in,
                              void* d_out, int out_size)
{
    const float* x   = (const float*)d_in[0];
    const float* Wq  = (const float*)d_in[1];
    const float* bq  = (const float*)d_in[2];
    const float* Wk  = (const float*)d_in[3];
    const float* bk  = (const float*)d_in[4];
    const float* Wv  = (const float*)d_in[5];
    const float* bv  = (const float*)d_in[6];
    const float* Wg  = (const float*)d_in[7];
    const float* bg  = (const float*)d_in[8];
    const float* Wo  = (const float*)d_in[9];
    const float* bo  = (const float*)d_in[10];
    const float* Wu1 = (const float*)d_in[11];
    const float* bu1 = (const float*)d_in[12];
    const float* Wu2 = (const float*)d_in[13];
    const float* bu2 = (const float*)d_in[14];

    float* out       = (float*)d_out;
    float* z_out     = out;
    float* attn_out  = out + 8192;
    float* sigma_out = out + 8192 + (size_t)Bq*NHq*Mq*Mq;

    cudaFuncSetAttribute(attn4_kernel,
        cudaFuncAttributeMaxDynamicSharedMemorySize, ATTN4_SMEM);
    cudaFuncSetAttribute(proj_mma_kernel,
        cudaFuncAttributeMaxDynamicSharedMemorySize, GEMM_SMEM);
    cudaFuncSetAttribute(sigma_mma_kernel,
        cudaFuncAttributeMaxDynamicSharedMemorySize, GEMM_SMEM);

    splitx_kernel<<<8192, 256>>>(x);
    tsplitw_kernel<<<dim3(32, 32, 5), 256>>>(Wq, Wk, Wv, Wg, Wu1);
    sigma_mma_kernel<<<64, 512, GEMM_SMEM>>>(bu1, Wu2, bu2, sigma_out);
    proj_mma_kernel<<<dim3(4, 64, 4), 512, GEMM_SMEM>>>(bq, bk, bv, bg);
    transv_kernel<<<dim3(16, 128), 256>>>();
    attn4_kernel<<<dim3(32, 16, 8), 256, ATTN4_SMEM>>>(sigma_out, attn_out);
    mean_kernel<<<128, 256>>>();
    z_kernel<<<dim3(4, 8), 256>>>(Wo, bo, z_out);
}